// round 1
// baseline (speedup 1.0000x reference)
#include <cuda_runtime.h>

// ---------------------------------------------------------------------------
// 2-layer ConvLSTM2D.  B=8, T=10, H=W=64, F=64 hidden, gates=256 (i,f,g,o).
// Layer recurrence as implicit GEMM: M=32768 pixels, N=256 gates,
// K = taps*64 (9 taps for layer0 recurrent, 18 taps for layer1 fused
// input+recurrent).  Layer0's Cin=1 input conv is folded into the pointwise.
// ---------------------------------------------------------------------------

#define HWPIX 4096                  // 64*64
#define CH 64
#define NPIX (8 * HWPIX)            // 32768
#define HC_ELEMS (NPIX * CH)        // 2097152
#define SEQ_ELEMS (10 * HC_ELEMS)   // 20971520
#define Z_ELEMS (NPIX * 256)        // 8388608

__device__ float g_h0[HC_ELEMS];
__device__ float g_c0[HC_ELEMS];
__device__ float g_h1[HC_ELEMS];
__device__ float g_c1[HC_ELEMS];
__device__ float g_seq0[SEQ_ELEMS]; // layer0 output sequence (b,t,y,x,f)
__device__ float g_z[Z_ELEMS];      // per-step gate pre-activations

__global__ void zero_state_kernel() {
    int i = blockIdx.x * 256 + threadIdx.x;
    g_h0[i] = 0.f; g_c0[i] = 0.f; g_h1[i] = 0.f; g_c1[i] = 0.f;
}

// ---------------------------------------------------------------------------
// Implicit-GEMM conv: Z[m][n] = sum over taps/channels of gathered src * W.
// Tile: BM=128 pixels x BN=128 gates, 256 threads, 8x8 accum per thread.
// K is consumed in chunks of 32 channels (2 chunks per 64-ch tap).
// FUSED=1: taps 0..8 read seq0[t] with WX(k1), taps 9..17 read h1 with WH(rk1).
// FUSED=0: taps 0..8 read h0 with WH(rk0).
// ---------------------------------------------------------------------------
template<int FUSED>
__global__ __launch_bounds__(256, 2)
void gemm_conv_kernel(int t, const float* __restrict__ WX,
                      const float* __restrict__ WH)
{
    __shared__ float As[128 * 36];   // 128 pixels x 32 ch (stride 36)
    __shared__ float Bs[32 * 132];   // 32 ch x 128 gates (stride 132)

    const int tid = threadIdx.x;
    const int bm = blockIdx.x;       // 0..255
    const int bn = blockIdx.y;       // 0..1
    const int tx = tid & 15;
    const int ty = tid >> 4;

    // A-load mapping: 2 threads per pixel-row, 16 floats each
    const int rowA  = tid >> 1;            // 0..127
    const int halfA = (tid & 1) * 16;      // 0 or 16
    const int m  = bm * 128 + rowA;
    const int ab = m >> 12;                // batch
    const int ay = (m >> 6) & 63;
    const int ax = m & 63;

    // B-load mapping: 8 threads per ci-row, 16 floats each
    const int rowB = tid >> 3;             // 0..31
    const int qB   = (tid & 7) * 16;

    float acc[8][8];
    #pragma unroll
    for (int i = 0; i < 8; i++)
        #pragma unroll
        for (int j = 0; j < 8; j++) acc[i][j] = 0.f;

    const int ntap = FUSED ? 18 : 9;
    for (int tap = 0; tap < ntap; ++tap) {
        const float* src; const float* W; long long bstr; int t9;
        if (FUSED && tap < 9) {
            t9 = tap;
            src = g_seq0 + (long long)t * (HWPIX * CH);
            bstr = (long long)10 * HWPIX * CH;     // batch stride in seq0
            W = WX + tap * (64 * 256);
        } else {
            t9 = FUSED ? tap - 9 : tap;
            src = FUSED ? g_h1 : g_h0;
            bstr = (long long)HWPIX * CH;
            W = WH + t9 * (64 * 256);
        }
        const int dy = t9 / 3 - 1, dx = t9 % 3 - 1;
        const int yy = ay + dy, xx = ax + dx;
        const bool inb = ((unsigned)yy < 64u) && ((unsigned)xx < 64u);
        const float* abase = src + (long long)ab * bstr
                           + ((yy << 6) + xx) * CH + halfA;

        for (int kc = 0; kc < 2; ++kc) {
            // ---- load A chunk (128 x 32) ----
            if (inb) {
                const float4* p = (const float4*)(abase + kc * 32);
                #pragma unroll
                for (int i = 0; i < 4; i++)
                    *(float4*)&As[rowA * 36 + halfA + i * 4] = p[i];
            } else {
                const float4 zz = make_float4(0.f, 0.f, 0.f, 0.f);
                #pragma unroll
                for (int i = 0; i < 4; i++)
                    *(float4*)&As[rowA * 36 + halfA + i * 4] = zz;
            }
            // ---- load B chunk (32 x 128) ----
            {
                const int ci = kc * 32 + rowB;
                const float4* p = (const float4*)(W + ci * 256 + bn * 128 + qB);
                #pragma unroll
                for (int i = 0; i < 4; i++)
                    *(float4*)&Bs[rowB * 132 + qB + i * 4] = p[i];
            }
            __syncthreads();

            #pragma unroll 4
            for (int k = 0; k < 32; ++k) {
                float a[8], b[8];
                #pragma unroll
                for (int i = 0; i < 8; i++) a[i] = As[(ty + i * 16) * 36 + k];
                #pragma unroll
                for (int j = 0; j < 8; j++) b[j] = Bs[k * 132 + tx + j * 16];
                #pragma unroll
                for (int i = 0; i < 8; i++)
                    #pragma unroll
                    for (int j = 0; j < 8; j++)
                        acc[i][j] = fmaf(a[i], b[j], acc[i][j]);
            }
            __syncthreads();
        }
    }

    // ---- store Z ----
    #pragma unroll
    for (int i = 0; i < 8; i++) {
        const int mm = bm * 128 + ty + i * 16;
        #pragma unroll
        for (int j = 0; j < 8; j++)
            g_z[mm * 256 + bn * 128 + tx + j * 16] = acc[i][j];
    }
}

// ---------------------------------------------------------------------------
// Pointwise LSTM update.  LAYER0=1 also adds the Cin=1 input conv (x * k0)
// and writes h into the seq0 buffer for layer1 consumption.
// ---------------------------------------------------------------------------
__device__ __forceinline__ float hsig(float v) {
    return fminf(fmaxf(0.2f * v + 0.5f, 0.f), 1.f);
}

template<int LAYER0>
__global__ void pointwise_kernel(int t, const float* __restrict__ bias,
                                 const float* __restrict__ xin,
                                 const float* __restrict__ k0)
{
    const int idx = blockIdx.x * 256 + threadIdx.x;   // < 2097152
    const int f   = idx & 63;
    const int pix = idx >> 6;
    const int b   = pix >> 12;
    const int y   = (pix >> 6) & 63;
    const int x   = pix & 63;

    float zi = g_z[pix * 256 + f]       + bias[f];
    float zf = g_z[pix * 256 + 64 + f]  + bias[64 + f];
    float zg = g_z[pix * 256 + 128 + f] + bias[128 + f];
    float zo = g_z[pix * 256 + 192 + f] + bias[192 + f];

    if (LAYER0) {
        // input conv: Cin=1, 3x3, SAME padding. x layout (b,t,y,x).
        #pragma unroll
        for (int tap = 0; tap < 9; ++tap) {
            const int dy = tap / 3 - 1, dx = tap % 3 - 1;
            const int yy = y + dy, xx = x + dx;
            if ((unsigned)yy < 64u && (unsigned)xx < 64u) {
                const float xv = __ldg(&xin[((long long)b * 10 + t) * HWPIX
                                            + yy * 64 + xx]);
                zi += xv * __ldg(&k0[tap * 256 + f]);
                zf += xv * __ldg(&k0[tap * 256 + 64 + f]);
                zg += xv * __ldg(&k0[tap * 256 + 128 + f]);
                zo += xv * __ldg(&k0[tap * 256 + 192 + f]);
            }
        }
    }

    float* hbuf = LAYER0 ? g_h0 : g_h1;
    float* cbuf = LAYER0 ? g_c0 : g_c1;

    const float cp = cbuf[idx];
    const float cn = hsig(zf) * cp + hsig(zi) * tanhf(zg);
    const float hn = hsig(zo) * tanhf(cn);
    cbuf[idx] = cn;
    hbuf[idx] = hn;

    if (LAYER0) {
        // seq0 layout: (b, t, y, x, f)
        g_seq0[((long long)b * 10 + t) * (HWPIX * CH)
               + (pix & (HWPIX - 1)) * CH + f] = hn;
    }
}

// Output layout: stack([[h0,c0],[h1,c1]]) -> [h0, c0, h1, c1], each 2097152 f32
__global__ void copy_out_kernel(float* __restrict__ out)
{
    const int i = blockIdx.x * 256 + threadIdx.x;   // < 8388608
    const int r = i >> 21;
    const int local = i & (HC_ELEMS - 1);
    float v;
    if      (r == 0) v = g_h0[local];
    else if (r == 1) v = g_c0[local];
    else if (r == 2) v = g_h1[local];
    else             v = g_c1[local];
    out[i] = v;
}

// ---------------------------------------------------------------------------
extern "C" void kernel_launch(void* const* d_in, const int* in_sizes, int n_in,
                              void* d_out, int out_size)
{
    const float* x   = (const float*)d_in[0];  // (8,10,64,64,1)
    const float* k0  = (const float*)d_in[1];  // (3,3,1,256)
    const float* rk0 = (const float*)d_in[2];  // (3,3,64,256)
    const float* b0  = (const float*)d_in[3];  // (256,)
    const float* k1  = (const float*)d_in[4];  // (3,3,64,256)
    const float* rk1 = (const float*)d_in[5];  // (3,3,64,256)
    const float* b1  = (const float*)d_in[6];  // (256,)
    float* out = (float*)d_out;

    zero_state_kernel<<<HC_ELEMS / 256, 256>>>();

    const dim3 ggrid(256, 2);
    for (int t = 0; t < 10; ++t) {
        // layer 0: recurrent conv GEMM, then pointwise (adds x-conv + bias)
        gemm_conv_kernel<0><<<ggrid, 256>>>(t, nullptr, rk0);
        pointwise_kernel<1><<<HC_ELEMS / 256, 256>>>(t, b0, x, k0);
        // layer 1: fused input(seq0[t])+recurrent conv GEMM, then pointwise
        gemm_conv_kernel<1><<<ggrid, 256>>>(t, k1, rk1);
        pointwise_kernel<0><<<HC_ELEMS / 256, 256>>>(t, b1, nullptr, nullptr);
    }

    copy_out_kernel<<<(4 * HC_ELEMS) / 256, 256>>>(out);
}

// round 3
// speedup vs baseline: 2.6078x; 2.6078x over previous
#include <cuda_runtime.h>

// ---------------------------------------------------------------------------
// 2-layer ConvLSTM2D.  B=8, T=10, H=W=64, F=64 hidden, gates=256 (i,f,g,o).
// Recurrence as implicit GEMM on TF32 tensor cores (mma.sync.m16n8k8):
//   M=32768 pixels, N=256 gates, K = taps*64 (9 taps layer0, 18 taps layer1
//   fused input+recurrent).  Layer0's Cin=1 input conv folded into pointwise.
// ---------------------------------------------------------------------------

#define HWPIX 4096                  // 64*64
#define CH 64
#define NPIX (8 * HWPIX)            // 32768
#define HC_ELEMS (NPIX * CH)        // 2097152
#define SEQ_ELEMS (10 * HC_ELEMS)   // 20971520
#define Z_ELEMS (NPIX * 256)        // 8388608

__device__ float g_h0[HC_ELEMS];
__device__ float g_c0[HC_ELEMS];
__device__ float g_h1[HC_ELEMS];
__device__ float g_c1[HC_ELEMS];
__device__ float g_seq0[SEQ_ELEMS]; // layer0 output sequence (b,t,y,x,f)
__device__ float g_z[Z_ELEMS];      // per-step gate pre-activations

__global__ void zero_state_kernel() {
    int i = blockIdx.x * 256 + threadIdx.x;
    g_h0[i] = 0.f; g_c0[i] = 0.f; g_h1[i] = 0.f; g_c1[i] = 0.f;
}

__device__ __forceinline__ float to_tf32(float x) {
    float r;
    asm("cvt.rna.tf32.f32 %0, %1;" : "=f"(r) : "f"(x));
    return r;
}

__device__ __forceinline__ void mma_tf32(float c[4], const float a[4],
                                         const float b[2]) {
    asm volatile(
        "mma.sync.aligned.m16n8k8.row.col.f32.tf32.tf32.f32 "
        "{%0,%1,%2,%3}, {%4,%5,%6,%7}, {%8,%9}, {%0,%1,%2,%3};"
        : "+f"(c[0]), "+f"(c[1]), "+f"(c[2]), "+f"(c[3])
        : "r"(__float_as_uint(a[0])), "r"(__float_as_uint(a[1])),
          "r"(__float_as_uint(a[2])), "r"(__float_as_uint(a[3])),
          "r"(__float_as_uint(b[0])), "r"(__float_as_uint(b[1])));
}

// ---------------------------------------------------------------------------
// Implicit-GEMM conv on TF32 tensor cores.
// CTA tile 128x128, BK=32, 8 warps in 2(M)x4(N) grid, warp tile 64x32.
// Per warp: 4x4 m16n8k8 tiles, fp32 accumulate.
// FUSED=1: taps 0..8 read seq0[t] with WX(k1), taps 9..17 read h1 with WH(rk1).
// FUSED=0: taps 0..8 read h0 with WH(rk0).
// ---------------------------------------------------------------------------
template<int FUSED>
__global__ __launch_bounds__(256, 2)
void gemm_conv_tc(int t, const float* __restrict__ WX,
                  const float* __restrict__ WH)
{
    __shared__ float As[128 * 36];   // 128 pixels x 32 ch  (stride 36: bank-free)
    __shared__ float Bs[32 * 136];   // 32 ch x 128 gates   (stride 136: bank-free)

    const int tid  = threadIdx.x;
    const int wid  = tid >> 5;
    const int lane = tid & 31;
    const int lr   = lane >> 2;      // 0..7
    const int lc   = lane & 3;       // 0..3
    const int warp_m = (wid >> 2) * 64;   // 0 or 64
    const int warp_n = (wid & 3) * 32;    // 0,32,64,96

    const int bm = blockIdx.x;       // 0..255
    const int bn = blockIdx.y;       // 0..1

    // A-load mapping: 2 threads per pixel-row, 16 floats each
    const int rowA  = tid >> 1;            // 0..127
    const int halfA = (tid & 1) * 16;      // 0 or 16
    const int m  = bm * 128 + rowA;
    const int ab = m >> 12;                // batch
    const int ay = (m >> 6) & 63;
    const int ax = m & 63;

    // B-load mapping: 8 threads per ci-row, 16 floats each
    const int rowB = tid >> 3;             // 0..31
    const int qB   = (tid & 7) * 16;

    float acc[4][4][4];
    #pragma unroll
    for (int i = 0; i < 4; i++)
        #pragma unroll
        for (int j = 0; j < 4; j++)
            #pragma unroll
            for (int r = 0; r < 4; r++) acc[i][j][r] = 0.f;

    const int ntap = FUSED ? 18 : 9;
    for (int tap = 0; tap < ntap; ++tap) {
        const float* src; const float* W; long long bstr; int t9;
        if (FUSED && tap < 9) {
            t9 = tap;
            src = g_seq0 + (long long)t * (HWPIX * CH);
            bstr = (long long)10 * HWPIX * CH;     // batch stride in seq0
            W = WX + tap * (64 * 256);
        } else {
            t9 = FUSED ? tap - 9 : tap;
            src = FUSED ? g_h1 : g_h0;
            bstr = (long long)HWPIX * CH;
            W = WH + t9 * (64 * 256);
        }
        const int dy = t9 / 3 - 1, dx = t9 % 3 - 1;
        const int yy = ay + dy, xx = ax + dx;
        const bool inb = ((unsigned)yy < 64u) && ((unsigned)xx < 64u);
        const float* abase = src + (long long)ab * bstr
                           + ((yy << 6) + xx) * CH + halfA;

        for (int kc = 0; kc < 2; ++kc) {
            // ---- load A chunk (128 x 32), round to tf32 ----
            if (inb) {
                const float4* p = (const float4*)(abase + kc * 32);
                #pragma unroll
                for (int i = 0; i < 4; i++) {
                    float4 v = p[i];
                    v.x = to_tf32(v.x); v.y = to_tf32(v.y);
                    v.z = to_tf32(v.z); v.w = to_tf32(v.w);
                    *(float4*)&As[rowA * 36 + halfA + i * 4] = v;
                }
            } else {
                const float4 zz = make_float4(0.f, 0.f, 0.f, 0.f);
                #pragma unroll
                for (int i = 0; i < 4; i++)
                    *(float4*)&As[rowA * 36 + halfA + i * 4] = zz;
            }
            // ---- load B chunk (32 x 128), round to tf32 ----
            {
                const int ci = kc * 32 + rowB;
                const float4* p = (const float4*)(W + ci * 256 + bn * 128 + qB);
                #pragma unroll
                for (int i = 0; i < 4; i++) {
                    float4 v = p[i];
                    v.x = to_tf32(v.x); v.y = to_tf32(v.y);
                    v.z = to_tf32(v.z); v.w = to_tf32(v.w);
                    *(float4*)&Bs[rowB * 136 + qB + i * 4] = v;
                }
            }
            __syncthreads();

            #pragma unroll
            for (int ks = 0; ks < 4; ++ks) {
                const int k0 = ks * 8;
                float a[4][4], b[4][2];
                #pragma unroll
                for (int i = 0; i < 4; i++) {
                    const int row = warp_m + i * 16 + lr;
                    a[i][0] = As[row * 36 + k0 + lc];
                    a[i][1] = As[(row + 8) * 36 + k0 + lc];
                    a[i][2] = As[row * 36 + k0 + lc + 4];
                    a[i][3] = As[(row + 8) * 36 + k0 + lc + 4];
                }
                #pragma unroll
                for (int j = 0; j < 4; j++) {
                    const int col = warp_n + j * 8 + lr;
                    b[j][0] = Bs[(k0 + lc) * 136 + col];
                    b[j][1] = Bs[(k0 + lc + 4) * 136 + col];
                }
                #pragma unroll
                for (int i = 0; i < 4; i++)
                    #pragma unroll
                    for (int j = 0; j < 4; j++)
                        mma_tf32(acc[i][j], a[i], b[j]);
            }
            __syncthreads();
        }
    }

    // ---- store Z ----
    #pragma unroll
    for (int i = 0; i < 4; i++) {
        const int mm = bm * 128 + warp_m + i * 16 + lr;
        #pragma unroll
        for (int j = 0; j < 4; j++) {
            const int col = bn * 128 + warp_n + j * 8 + 2 * lc;
            *(float2*)&g_z[mm * 256 + col] =
                make_float2(acc[i][j][0], acc[i][j][1]);
            *(float2*)&g_z[(mm + 8) * 256 + col] =
                make_float2(acc[i][j][2], acc[i][j][3]);
        }
    }
}

// ---------------------------------------------------------------------------
// Pointwise LSTM update.  LAYER0=1 also adds the Cin=1 input conv (x * k0)
// and writes h into the seq0 buffer for layer1 consumption.
// ---------------------------------------------------------------------------
__device__ __forceinline__ float hsig(float v) {
    return fminf(fmaxf(0.2f * v + 0.5f, 0.f), 1.f);
}

template<int LAYER0>
__global__ void pointwise_kernel(int t, const float* __restrict__ bias,
                                 const float* __restrict__ xin,
                                 const float* __restrict__ k0)
{
    const int idx = blockIdx.x * 256 + threadIdx.x;   // < 2097152
    const int f   = idx & 63;
    const int pix = idx >> 6;
    const int b   = pix >> 12;
    const int y   = (pix >> 6) & 63;
    const int x   = pix & 63;

    float zi = g_z[pix * 256 + f]       + bias[f];
    float zf = g_z[pix * 256 + 64 + f]  + bias[64 + f];
    float zg = g_z[pix * 256 + 128 + f] + bias[128 + f];
    float zo = g_z[pix * 256 + 192 + f] + bias[192 + f];

    if (LAYER0) {
        // input conv: Cin=1, 3x3, SAME padding. x layout (b,t,y,x).
        #pragma unroll
        for (int tap = 0; tap < 9; ++tap) {
            const int dy = tap / 3 - 1, dx = tap % 3 - 1;
            const int yy = y + dy, xx = x + dx;
            if ((unsigned)yy < 64u && (unsigned)xx < 64u) {
                const float xv = __ldg(&xin[((long long)b * 10 + t) * HWPIX
                                            + yy * 64 + xx]);
                zi += xv * __ldg(&k0[tap * 256 + f]);
                zf += xv * __ldg(&k0[tap * 256 + 64 + f]);
                zg += xv * __ldg(&k0[tap * 256 + 128 + f]);
                zo += xv * __ldg(&k0[tap * 256 + 192 + f]);
            }
        }
    }

    float* hbuf = LAYER0 ? g_h0 : g_h1;
    float* cbuf = LAYER0 ? g_c0 : g_c1;

    const float cp = cbuf[idx];
    const float cn = hsig(zf) * cp + hsig(zi) * tanhf(zg);
    const float hn = hsig(zo) * tanhf(cn);
    cbuf[idx] = cn;
    hbuf[idx] = hn;

    if (LAYER0) {
        // seq0 layout: (b, t, y, x, f)
        g_seq0[((long long)b * 10 + t) * (HWPIX * CH)
               + (pix & (HWPIX - 1)) * CH + f] = hn;
    }
}

// Output layout: stack([[h0,c0],[h1,c1]]) -> [h0, c0, h1, c1], each 2097152 f32
__global__ void copy_out_kernel(float* __restrict__ out)
{
    const int i = blockIdx.x * 256 + threadIdx.x;   // < 8388608
    const int r = i >> 21;
    const int local = i & (HC_ELEMS - 1);
    float v;
    if      (r == 0) v = g_h0[local];
    else if (r == 1) v = g_c0[local];
    else if (r == 2) v = g_h1[local];
    else             v = g_c1[local];
    out[i] = v;
}

// ---------------------------------------------------------------------------
extern "C" void kernel_launch(void* const* d_in, const int* in_sizes, int n_in,
                              void* d_out, int out_size)
{
    const float* x   = (const float*)d_in[0];  // (8,10,64,64,1)
    const float* k0  = (const float*)d_in[1];  // (3,3,1,256)
    const float* rk0 = (const float*)d_in[2];  // (3,3,64,256)
    const float* b0  = (const float*)d_in[3];  // (256,)
    const float* k1  = (const float*)d_in[4];  // (3,3,64,256)
    const float* rk1 = (const float*)d_in[5];  // (3,3,64,256)
    const float* b1  = (const float*)d_in[6];  // (256,)
    float* out = (float*)d_out;

    zero_state_kernel<<<HC_ELEMS / 256, 256>>>();

    const dim3 ggrid(256, 2);
    for (int t = 0; t < 10; ++t) {
        // layer 0: recurrent conv GEMM, then pointwise (adds x-conv + bias)
        gemm_conv_tc<0><<<ggrid, 256>>>(t, nullptr, rk0);
        pointwise_kernel<1><<<HC_ELEMS / 256, 256>>>(t, b0, x, k0);
        // layer 1: fused input(seq0[t])+recurrent conv GEMM, then pointwise
        gemm_conv_tc<1><<<ggrid, 256>>>(t, k1, rk1);
        pointwise_kernel<0><<<HC_ELEMS / 256, 256>>>(t, b1, nullptr, nullptr);
    }

    copy_out_kernel<<<(4 * HC_ELEMS) / 256, 256>>>(out);
}

// round 9
// speedup vs baseline: 3.1601x; 1.2118x over previous
#include <cuda_runtime.h>
#include <cstdint>

// ---------------------------------------------------------------------------
// 2-layer ConvLSTM2D, tf32 mma.sync (scalar-LDS fragments) + cp.async
// double buffering.  CTA = 128 pixels x 256 gates (i,f,g,o), 8 warps
// (2m x 4n), warp tile 64x64 gate-interleaved.  LSTM pointwise fused into
// the epilogue in registers.  B pre-transposed/tf32-rounded in global;
// h / seq0 stored tf32-rounded so the A path is a pure cp.async copy.
// NOTE: all __device__ state buffers are selected INSIDE device code
// (host code must never take the address of a __device__ symbol).
// ---------------------------------------------------------------------------

#define HWPIX 4096
#define NPIX 32768
#define HC_ELEMS (NPIX * 64)
#define SEQ_ELEMS (10 * HC_ELEMS)
#define BIMG 8192                    // floats per B image [32 k][256 n]

__device__ float g_h0a[HC_ELEMS];
__device__ float g_h0b[HC_ELEMS];
__device__ float g_h1a[HC_ELEMS];
__device__ float g_h1b[HC_ELEMS];
__device__ float g_c0[HC_ELEMS];
__device__ float g_c1[HC_ELEMS];
__device__ float g_seq0[SEQ_ELEMS];  // (b,t,y,x,f), tf32-rounded
__device__ float g_Bw0[18 * BIMG];   // layer0 B images
__device__ float g_Bw1[36 * BIMG];   // layer1 B images

// ------------------------------ helpers ------------------------------------
__device__ __forceinline__ uint32_t smem_u32(const void* p) {
    uint32_t a;
    asm("{ .reg .u64 t; cvta.to.shared.u64 t, %1; cvt.u32.u64 %0, t; }"
        : "=r"(a) : "l"(p));
    return a;
}
__device__ __forceinline__ float to_tf32(float x) {
    float r; asm("cvt.rna.tf32.f32 %0, %1;" : "=f"(r) : "f"(x)); return r;
}
__device__ __forceinline__ float hsig(float v) {
    return fminf(fmaxf(0.2f * v + 0.5f, 0.f), 1.f);
}
__device__ __forceinline__ void mma_tf32(float c[4], const float a[4],
                                         float b0, float b1) {
    asm volatile(
        "mma.sync.aligned.m16n8k8.row.col.f32.tf32.tf32.f32 "
        "{%0,%1,%2,%3}, {%4,%5,%6,%7}, {%8,%9}, {%0,%1,%2,%3};"
        : "+f"(c[0]), "+f"(c[1]), "+f"(c[2]), "+f"(c[3])
        : "r"(__float_as_uint(a[0])), "r"(__float_as_uint(a[1])),
          "r"(__float_as_uint(a[2])), "r"(__float_as_uint(a[3])),
          "r"(__float_as_uint(b0)), "r"(__float_as_uint(b1)));
}
#define CP_COMMIT() asm volatile("cp.async.commit_group;" ::: "memory")
#define CP_WAIT1()  asm volatile("cp.async.wait_group 1;" ::: "memory")

// ------------------------------ small kernels ------------------------------
__global__ void zero_state_kernel() {
    int i = blockIdx.x * 256 + threadIdx.x;
    g_h0a[i] = 0.f; g_h1a[i] = 0.f; g_c0[i] = 0.f; g_c1[i] = 0.f;
}

// B images: [k 32][n 256] per (tap, kc) chunk, tf32-rounded.
__global__ void prep_weights(const float* __restrict__ rk0,
                             const float* __restrict__ k1,
                             const float* __restrict__ rk1) {
    const int i = blockIdx.x * 256 + threadIdx.x;   // < 54*8192
    const int img = i >> 13;
    const int e = i & 8191;
    const int k = e >> 8, n = e & 255;
    float v; float* dst;
    if (img < 18) {
        const int tap = img >> 1, kc = img & 1;
        v = rk0[(tap * 64 + kc * 32 + k) * 256 + n];
        dst = g_Bw0 + img * BIMG;
    } else {
        const int c = img - 18, tap = c >> 1, kc = c & 1;
        v = (tap < 9) ? k1[(tap * 64 + kc * 32 + k) * 256 + n]
                      : rk1[((tap - 9) * 64 + kc * 32 + k) * 256 + n];
        dst = g_Bw1 + c * BIMG;
    }
    dst[k * 256 + n] = to_tf32(v);
}

__global__ void copy_out_kernel(float* __restrict__ out, int pp) {
    const int i = blockIdx.x * 256 + threadIdx.x;
    const int r = i >> 21;
    const int local = i & (HC_ELEMS - 1);
    // final h lives in the buffer written at t=9: pp = 9&1 = 1 -> "a" buffers
    float v;
    if      (r == 0) v = pp ? g_h0a[local] : g_h0b[local];
    else if (r == 1) v = g_c0[local];
    else if (r == 2) v = pp ? g_h1a[local] : g_h1b[local];
    else             v = g_c1[local];
    out[i] = v;
}

// ------------------------------ main kernel --------------------------------
// smem: A ping/pong 128x36 f32 (18432B each) at 0/18432,
//       B ping/pong 32x264 f32 (33792B each) at 36864/70656.  Total 104448B.
template<int LAYER>
__global__ __launch_bounds__(256, 1)
void convlstm_step(int t, int pp,
                   const float* __restrict__ bias,
                   const float* __restrict__ xin,
                   const float* __restrict__ k0g)
{
    // --- state buffers selected in DEVICE code (host must not pass them) ---
    const float* hprev;
    float* hnext;
    float* cbuf;
    if (LAYER == 0) {
        hprev = pp ? g_h0b : g_h0a;
        hnext = pp ? g_h0a : g_h0b;
        cbuf  = g_c0;
    } else {
        hprev = pp ? g_h1b : g_h1a;
        hnext = pp ? g_h1a : g_h1b;
        cbuf  = g_c1;
    }

    extern __shared__ float smem[];
    const uint32_t sbase = smem_u32(smem);
    const uint32_t sA[2] = { sbase, sbase + 18432u };
    const uint32_t sB[2] = { sbase + 36864u, sbase + 70656u };
    float* fA[2] = { smem, smem + 4608 };
    float* fB[2] = { smem + 9216, smem + 17664 };

    const int tid = threadIdx.x;
    const int lane = tid & 31, wid = tid >> 5;
    const int lr = lane >> 2, lc = lane & 3;
    const int wm = (wid >> 2) * 64;          // warp m-base: 0 or 64
    const int wn16 = (wid & 3) * 16;         // warp n-base within each gate
    const int bm = blockIdx.x;               // 0..255

    // A-loader mapping: 2 threads per pixel row, 16 f32 (64B) each
    const int rowA = tid >> 1;
    const int halfA = (tid & 1) * 16;
    const int m = bm * 128 + rowA;
    const int ab = m >> 12, ay = (m >> 6) & 63, ax = m & 63;

    const float* BW = (LAYER == 0) ? g_Bw0 : g_Bw1;
    const int NCH = (LAYER == 0) ? 18 : 36;

    float acc[4][8][4];
    #pragma unroll
    for (int i = 0; i < 4; i++)
        #pragma unroll
        for (int j = 0; j < 8; j++)
            #pragma unroll
            for (int r = 0; r < 4; r++) acc[i][j][r] = 0.f;

    // ---- async loaders ----
    auto issueB = [&](int ci, int buf) {
        const char* src = (const char*)(BW + ci * BIMG);
        const uint32_t dstb = sB[buf];
        #pragma unroll
        for (int q = 0; q < 8; q++) {
            const int c = tid + q * 256;          // 0..2047 16B-chunks
            const int row = c >> 6, off = (c & 63) * 16;
            asm volatile("cp.async.ca.shared.global [%0], [%1], 16;"
                :: "r"(dstb + row * 1056 + off), "l"(src + row * 1024 + off)
                : "memory");
        }
    };
    auto issueA = [&](int ci, int buf) {
        int tap = ci >> 1;
        const int kc = ci & 1;
        const float* src; long long bstr;
        if (LAYER == 1 && tap < 9) {
            src = g_seq0 + (long long)t * (HWPIX * 64);
            bstr = (long long)10 * HWPIX * 64;
        } else {
            if (LAYER == 1) tap -= 9;
            src = hprev; bstr = (long long)HWPIX * 64;
        }
        const int dy = tap / 3 - 1, dx = tap % 3 - 1;
        const int yy = ay + dy, xx = ax + dx;
        const bool inb = ((unsigned)yy < 64u) && ((unsigned)xx < 64u);
        const int pr = inb ? 16 : 0;
        const int yc = min(max(yy, 0), 63), xc = min(max(xx, 0), 63);
        const char* ap = (const char*)(src + (long long)ab * bstr
                        + ((yc << 6) + xc) * 64 + kc * 32 + halfA);
        const uint32_t dst = sA[buf] + rowA * 144 + halfA * 4;
        #pragma unroll
        for (int q = 0; q < 4; q++)
            asm volatile("cp.async.ca.shared.global [%0], [%1], 16, %2;"
                :: "r"(dst + q * 16), "l"(ap + q * 16), "r"(pr) : "memory");
    };

    issueA(0, 0);
    issueB(0, 0);
    CP_COMMIT();

    // ---- main loop ----
    #pragma unroll 1
    for (int ci = 0; ci < NCH; ci++) {
        const int buf = ci & 1;
        if (ci + 1 < NCH) { issueA(ci + 1, buf ^ 1); issueB(ci + 1, buf ^ 1); }
        CP_COMMIT();
        CP_WAIT1();
        __syncthreads();

        const float* As = fA[buf];
        const float* Bs = fB[buf];
        #pragma unroll
        for (int ks = 0; ks < 4; ks++) {
            const int kk = ks * 8;
            float a[4][4], b[8][2];
            #pragma unroll
            for (int i = 0; i < 4; i++) {
                const int row = wm + i * 16 + lr;
                a[i][0] = As[row * 36 + kk + lc];
                a[i][1] = As[(row + 8) * 36 + kk + lc];
                a[i][2] = As[row * 36 + kk + lc + 4];
                a[i][3] = As[(row + 8) * 36 + kk + lc + 4];
            }
            #pragma unroll
            for (int j = 0; j < 8; j++) {
                const int col = (j >> 1) * 64 + wn16 + (j & 1) * 8 + lr;
                b[j][0] = Bs[(kk + lc) * 264 + col];
                b[j][1] = Bs[(kk + lc + 4) * 264 + col];
            }
            #pragma unroll
            for (int i = 0; i < 4; i++)
                #pragma unroll
                for (int j = 0; j < 8; j++)
                    mma_tf32(acc[i][j], a[i], b[j][0], b[j][1]);
        }
        __syncthreads();
    }

    // ---- fused LSTM epilogue: all 4 gates in-register per thread ----
    #pragma unroll
    for (int i = 0; i < 4; i++) {
        #pragma unroll
        for (int rp = 0; rp < 2; rp++) {
            const int pix = bm * 128 + wm + i * 16 + lr + rp * 8;
            const int r0 = rp * 2;
            float xv[9];
            if (LAYER == 0) {
                const int bb = pix >> 12, y = (pix >> 6) & 63, x = pix & 63;
                #pragma unroll
                for (int tap = 0; tap < 9; tap++) {
                    const int dy = tap / 3 - 1, dx = tap % 3 - 1;
                    const int yy = y + dy, xx = x + dx;
                    xv[tap] = (((unsigned)yy < 64u) && ((unsigned)xx < 64u))
                        ? __ldg(&xin[(long long)(bb * 10 + t) * HWPIX
                                     + yy * 64 + xx])
                        : 0.f;
                }
            }
            #pragma unroll
            for (int jj = 0; jj < 2; jj++) {
                const int f = wn16 + jj * 8 + 2 * lc;
                #pragma unroll
                for (int u = 0; u < 2; u++) {
                    float zi = acc[i][jj][r0 + u]     + __ldg(&bias[f + u]);
                    float zf = acc[i][2 + jj][r0 + u] + __ldg(&bias[64 + f + u]);
                    float zg = acc[i][4 + jj][r0 + u] + __ldg(&bias[128 + f + u]);
                    float zo = acc[i][6 + jj][r0 + u] + __ldg(&bias[192 + f + u]);
                    if (LAYER == 0) {
                        #pragma unroll
                        for (int tap = 0; tap < 9; tap++) {
                            const float kx = xv[tap];
                            zi = fmaf(kx, __ldg(&k0g[tap * 256 + f + u]), zi);
                            zf = fmaf(kx, __ldg(&k0g[tap * 256 + 64 + f + u]), zf);
                            zg = fmaf(kx, __ldg(&k0g[tap * 256 + 128 + f + u]), zg);
                            zo = fmaf(kx, __ldg(&k0g[tap * 256 + 192 + f + u]), zo);
                        }
                    }
                    const long long base = (long long)pix * 64 + f + u;
                    const float cp = cbuf[base];
                    const float cn = hsig(zf) * cp + hsig(zi) * tanhf(zg);
                    const float hn = hsig(zo) * tanhf(cn);
                    cbuf[base] = cn;
                    const float hr = to_tf32(hn);
                    hnext[base] = hr;
                    if (LAYER == 0) {
                        g_seq0[((long long)((pix >> 12) * 10 + t) * HWPIX
                                + (pix & 4095)) * 64 + f + u] = hr;
                    }
                }
            }
        }
    }
}

// ---------------------------------------------------------------------------
extern "C" void kernel_launch(void* const* d_in, const int* in_sizes, int n_in,
                              void* d_out, int out_size)
{
    const float* x   = (const float*)d_in[0];
    const float* k0  = (const float*)d_in[1];
    const float* rk0 = (const float*)d_in[2];
    const float* b0  = (const float*)d_in[3];
    const float* k1  = (const float*)d_in[4];
    const float* rk1 = (const float*)d_in[5];
    const float* b1  = (const float*)d_in[6];
    float* out = (float*)d_out;

    cudaFuncSetAttribute(convlstm_step<0>,
                         cudaFuncAttributeMaxDynamicSharedMemorySize, 104448);
    cudaFuncSetAttribute(convlstm_step<1>,
                         cudaFuncAttributeMaxDynamicSharedMemorySize, 104448);

    zero_state_kernel<<<HC_ELEMS / 256, 256>>>();
    prep_weights<<<(54 * BIMG) / 256, 256>>>(rk0, k1, rk1);

    for (int t = 0; t < 10; ++t) {
        const int pp = t & 1;
        convlstm_step<0><<<256, 256, 104448>>>(t, pp, b0, x, k0);
        convlstm_step<1><<<256, 256, 104448>>>(t, pp, b1, nullptr, nullptr);
    }

    // t=9 wrote with pp=1 -> "a" buffers hold final h
    copy_out_kernel<<<(4 * HC_ELEMS) / 256, 256>>>(out, 1);
}

// round 10
// speedup vs baseline: 3.4982x; 1.1070x over previous
#include <cuda_runtime.h>
#include <cstdint>

// ---------------------------------------------------------------------------
// 2-layer ConvLSTM2D, tf32 mma.sync + ldmatrix.x4 fragments + cp.async
// double buffering.  CTA = 128 pixels x 256 gates (i,f,g,o), 8 warps
// (2m x 4n), warp tile 64x64 gate-interleaved.  LSTM pointwise fused into
// the epilogue in registers.  B pre-transposed [n][k]/tf32-rounded in
// global; h / seq0 stored tf32-rounded so the A path is a pure cp.async copy.
// State buffers selected INSIDE device code (never pass __device__ symbol
// addresses from host).
// ---------------------------------------------------------------------------

#define HWPIX 4096
#define NPIX 32768
#define HC_ELEMS (NPIX * 64)
#define SEQ_ELEMS (10 * HC_ELEMS)
#define IMGF 9216                    // floats per B image: 256 n-rows x 36 k

__device__ float g_h0a[HC_ELEMS];
__device__ float g_h0b[HC_ELEMS];
__device__ float g_h1a[HC_ELEMS];
__device__ float g_h1b[HC_ELEMS];
__device__ float g_c0[HC_ELEMS];
__device__ float g_c1[HC_ELEMS];
__device__ float g_seq0[SEQ_ELEMS];  // (b,t,y,x,f), tf32-rounded
__device__ float g_Bw0[18 * IMGF];   // layer0 B images [n][36]
__device__ float g_Bw1[36 * IMGF];   // layer1 B images [n][36]

// ------------------------------ helpers ------------------------------------
__device__ __forceinline__ uint32_t smem_u32(const void* p) {
    uint32_t a;
    asm("{ .reg .u64 t; cvta.to.shared.u64 t, %1; cvt.u32.u64 %0, t; }"
        : "=r"(a) : "l"(p));
    return a;
}
__device__ __forceinline__ float to_tf32(float x) {
    float r; asm("cvt.rna.tf32.f32 %0, %1;" : "=f"(r) : "f"(x)); return r;
}
__device__ __forceinline__ float hsig(float v) {
    return fminf(fmaxf(0.2f * v + 0.5f, 0.f), 1.f);
}
__device__ __forceinline__ void mma_tf32u(float c[4], const uint32_t a[4],
                                          uint32_t b0, uint32_t b1) {
    asm volatile(
        "mma.sync.aligned.m16n8k8.row.col.f32.tf32.tf32.f32 "
        "{%0,%1,%2,%3}, {%4,%5,%6,%7}, {%8,%9}, {%0,%1,%2,%3};"
        : "+f"(c[0]), "+f"(c[1]), "+f"(c[2]), "+f"(c[3])
        : "r"(a[0]), "r"(a[1]), "r"(a[2]), "r"(a[3]), "r"(b0), "r"(b1));
}
#define LDSM4(r0, r1, r2, r3, addr) \
    asm volatile("ldmatrix.sync.aligned.m8n8.x4.shared.b16 {%0,%1,%2,%3}, [%4];" \
        : "=r"(r0), "=r"(r1), "=r"(r2), "=r"(r3) : "r"(addr))
#define CP_COMMIT() asm volatile("cp.async.commit_group;" ::: "memory")
#define CP_WAIT1()  asm volatile("cp.async.wait_group 1;" ::: "memory")

// ------------------------------ small kernels ------------------------------
__global__ void zero_state_kernel() {
    int i = blockIdx.x * 256 + threadIdx.x;
    g_h0a[i] = 0.f; g_h1a[i] = 0.f; g_c0[i] = 0.f; g_c1[i] = 0.f;
}

// B images: transposed [n 256][k 36 (pad, 32 valid)] per (tap,kc) chunk.
__global__ void prep_weights(const float* __restrict__ rk0,
                             const float* __restrict__ k1,
                             const float* __restrict__ rk1) {
    const int i = blockIdx.x * 256 + threadIdx.x;   // < 54*IMGF
    const int img = i / IMGF;
    const int e = i % IMGF;
    const int n = e / 36, k = e % 36;
    float v = 0.f; float* dst;
    if (img < 18) {
        const int tap = img >> 1, kc = img & 1;
        if (k < 32) v = rk0[(tap * 64 + kc * 32 + k) * 256 + n];
        dst = g_Bw0 + img * IMGF;
    } else {
        const int c = img - 18, tap = c >> 1, kc = c & 1;
        if (k < 32)
            v = (tap < 9) ? k1[(tap * 64 + kc * 32 + k) * 256 + n]
                          : rk1[((tap - 9) * 64 + kc * 32 + k) * 256 + n];
        dst = g_Bw1 + c * IMGF;
    }
    dst[n * 36 + k] = to_tf32(v);
}

__global__ void copy_out_kernel(float* __restrict__ out, int pp) {
    const int i = blockIdx.x * 256 + threadIdx.x;
    const int r = i >> 21;
    const int local = i & (HC_ELEMS - 1);
    float v;
    if      (r == 0) v = pp ? g_h0a[local] : g_h0b[local];
    else if (r == 1) v = g_c0[local];
    else if (r == 2) v = pp ? g_h1a[local] : g_h1b[local];
    else             v = g_c1[local];
    out[i] = v;
}

// ------------------------------ main kernel --------------------------------
// smem: A ping/pong 128x36 f32 (18432B) at 0/18432,
//       B ping/pong 256x36 f32 (36864B) at 36864/73728.  Total 110592B.
template<int LAYER>
__global__ __launch_bounds__(256, 1)
void convlstm_step(int t, int pp,
                   const float* __restrict__ bias,
                   const float* __restrict__ xin,
                   const float* __restrict__ k0g)
{
    const float* hprev; float* hnext; float* cbuf;
    if (LAYER == 0) {
        hprev = pp ? g_h0b : g_h0a;
        hnext = pp ? g_h0a : g_h0b;
        cbuf  = g_c0;
    } else {
        hprev = pp ? g_h1b : g_h1a;
        hnext = pp ? g_h1a : g_h1b;
        cbuf  = g_c1;
    }

    extern __shared__ float smem[];
    const uint32_t sbase = smem_u32(smem);
    const uint32_t sA[2] = { sbase, sbase + 18432u };
    const uint32_t sB[2] = { sbase + 36864u, sbase + 73728u };

    const int tid = threadIdx.x;
    const int lane = tid & 31, wid = tid >> 5;
    const int lr = lane >> 2, lc = lane & 3;
    const int wm = (wid >> 2) * 64;          // warp m-base: 0 or 64
    const int wn16 = (wid & 3) * 16;         // warp n-base within each gate
    const int bm = blockIdx.x;               // 0..255

    // A-loader mapping: 2 threads per pixel row, 16 f32 (64B) each
    const int rowA = tid >> 1;
    const int halfA = (tid & 1) * 16;
    const int m = bm * 128 + rowA;
    const int ab = m >> 12, ay = (m >> 6) & 63, ax = m & 63;

    const float* BW = (LAYER == 0) ? g_Bw0 : g_Bw1;
    const int NCH = (LAYER == 0) ? 18 : 36;

    float acc[4][8][4];
    #pragma unroll
    for (int i = 0; i < 4; i++)
        #pragma unroll
        for (int j = 0; j < 8; j++)
            #pragma unroll
            for (int r = 0; r < 4; r++) acc[i][j][r] = 0.f;

    // ---- async loaders ----
    auto issueB = [&](int ci, int buf) {
        const char* src = (const char*)(BW + ci * IMGF);
        const uint32_t dstb = sB[buf];
        #pragma unroll
        for (int q = 0; q < 9; q++) {
            const int idx = (tid + q * 256) * 16;     // 2304 x 16B = 36864B
            asm volatile("cp.async.ca.shared.global [%0], [%1], 16;"
                :: "r"(dstb + idx), "l"(src + idx) : "memory");
        }
    };
    auto issueA = [&](int ci, int buf) {
        int tap = ci >> 1;
        const int kc = ci & 1;
        const float* src; long long bstr;
        if (LAYER == 1 && tap < 9) {
            src = g_seq0 + (long long)t * (HWPIX * 64);
            bstr = (long long)10 * HWPIX * 64;
        } else {
            if (LAYER == 1) tap -= 9;
            src = hprev; bstr = (long long)HWPIX * 64;
        }
        const int dy = tap / 3 - 1, dx = tap % 3 - 1;
        const int yy = ay + dy, xx = ax + dx;
        const bool inb = ((unsigned)yy < 64u) && ((unsigned)xx < 64u);
        const int pr = inb ? 16 : 0;
        const int yc = min(max(yy, 0), 63), xc = min(max(xx, 0), 63);
        const char* ap = (const char*)(src + (long long)ab * bstr
                        + ((yc << 6) + xc) * 64 + kc * 32 + halfA);
        const uint32_t dst = sA[buf] + rowA * 144 + halfA * 4;
        #pragma unroll
        for (int q = 0; q < 4; q++)
            asm volatile("cp.async.ca.shared.global [%0], [%1], 16, %2;"
                :: "r"(dst + q * 16), "l"(ap + q * 16), "r"(pr) : "memory");
    };

    issueA(0, 0);
    issueB(0, 0);
    CP_COMMIT();

    // ---- main loop ----
    const int r16 = lane & 15;
    const int hi = (lane >> 4) * 16;
    #pragma unroll 1
    for (int ci = 0; ci < NCH; ci++) {
        const int buf = ci & 1;
        if (ci + 1 < NCH) { issueA(ci + 1, buf ^ 1); issueB(ci + 1, buf ^ 1); }
        CP_COMMIT();
        CP_WAIT1();
        __syncthreads();

        const uint32_t abase = sA[buf], bbase = sB[buf];
        #pragma unroll
        for (int ks = 0; ks < 4; ks++) {
            uint32_t a[4][4], b[4][4];
            #pragma unroll
            for (int i = 0; i < 4; i++) {
                const uint32_t ad = abase + (wm + i * 16 + r16) * 144
                                  + ks * 32 + hi;
                LDSM4(a[i][0], a[i][1], a[i][2], a[i][3], ad);
            }
            #pragma unroll
            for (int g = 0; g < 4; g++) {
                const uint32_t bd = bbase + (g * 64 + wn16 + r16) * 144
                                  + ks * 32 + hi;
                LDSM4(b[g][0], b[g][1], b[g][2], b[g][3], bd);
            }
            #pragma unroll
            for (int i = 0; i < 4; i++)
                #pragma unroll
                for (int g = 0; g < 4; g++) {
                    mma_tf32u(acc[i][g * 2 + 0], a[i], b[g][0], b[g][2]);
                    mma_tf32u(acc[i][g * 2 + 1], a[i], b[g][1], b[g][3]);
                }
        }
        __syncthreads();
    }

    // ---- fused LSTM epilogue: all 4 gates in-register per thread ----
    #pragma unroll
    for (int i = 0; i < 4; i++) {
        #pragma unroll
        for (int rp = 0; rp < 2; rp++) {
            const int pix = bm * 128 + wm + i * 16 + lr + rp * 8;
            const int r0 = rp * 2;
            float xv[9];
            if (LAYER == 0) {
                const int bb = pix >> 12, y = (pix >> 6) & 63, x = pix & 63;
                #pragma unroll
                for (int tap = 0; tap < 9; tap++) {
                    const int dy = tap / 3 - 1, dx = tap % 3 - 1;
                    const int yy = y + dy, xx = x + dx;
                    xv[tap] = (((unsigned)yy < 64u) && ((unsigned)xx < 64u))
                        ? __ldg(&xin[(long long)(bb * 10 + t) * HWPIX
                                     + yy * 64 + xx])
                        : 0.f;
                }
            }
            #pragma unroll
            for (int jj = 0; jj < 2; jj++) {
                const int f = wn16 + jj * 8 + 2 * lc;
                #pragma unroll
                for (int u = 0; u < 2; u++) {
                    float zi = acc[i][jj][r0 + u]     + __ldg(&bias[f + u]);
                    float zf = acc[i][2 + jj][r0 + u] + __ldg(&bias[64 + f + u]);
                    float zg = acc[i][4 + jj][r0 + u] + __ldg(&bias[128 + f + u]);
                    float zo = acc[i][6 + jj][r0 + u] + __ldg(&bias[192 + f + u]);
                    if (LAYER == 0) {
                        #pragma unroll
                        for (int tap = 0; tap < 9; tap++) {
                            const float kx = xv[tap];
                            zi = fmaf(kx, __ldg(&k0g[tap * 256 + f + u]), zi);
                            zf = fmaf(kx, __ldg(&k0g[tap * 256 + 64 + f + u]), zf);
                            zg = fmaf(kx, __ldg(&k0g[tap * 256 + 128 + f + u]), zg);
                            zo = fmaf(kx, __ldg(&k0g[tap * 256 + 192 + f + u]), zo);
                        }
                    }
                    const long long base = (long long)pix * 64 + f + u;
                    const float cp = cbuf[base];
                    const float cn = hsig(zf) * cp + hsig(zi) * tanhf(zg);
                    const float hn = hsig(zo) * tanhf(cn);
                    cbuf[base] = cn;
                    const float hr = to_tf32(hn);
                    hnext[base] = hr;
                    if (LAYER == 0) {
                        g_seq0[((long long)((pix >> 12) * 10 + t) * HWPIX
                                + (pix & 4095)) * 64 + f + u] = hr;
                    }
                }
            }
        }
    }
}

// ---------------------------------------------------------------------------
extern "C" void kernel_launch(void* const* d_in, const int* in_sizes, int n_in,
                              void* d_out, int out_size)
{
    const float* x   = (const float*)d_in[0];
    const float* k0  = (const float*)d_in[1];
    const float* rk0 = (const float*)d_in[2];
    const float* b0  = (const float*)d_in[3];
    const float* k1  = (const float*)d_in[4];
    const float* rk1 = (const float*)d_in[5];
    const float* b1  = (const float*)d_in[6];
    float* out = (float*)d_out;

    cudaFuncSetAttribute(convlstm_step<0>,
                         cudaFuncAttributeMaxDynamicSharedMemorySize, 110592);
    cudaFuncSetAttribute(convlstm_step<1>,
                         cudaFuncAttributeMaxDynamicSharedMemorySize, 110592);

    zero_state_kernel<<<HC_ELEMS / 256, 256>>>();
    prep_weights<<<(54 * IMGF) / 256, 256>>>(rk0, k1, rk1);

    for (int t = 0; t < 10; ++t) {
        const int pp = t & 1;
        convlstm_step<0><<<256, 256, 110592>>>(t, pp, b0, x, k0);
        convlstm_step<1><<<256, 256, 110592>>>(t, pp, b1, nullptr, nullptr);
    }

    // t=9 wrote with pp=1 -> "a" buffers hold final h
    copy_out_kernel<<<(4 * HC_ELEMS) / 256, 256>>>(out, 1);
}

// round 13
// speedup vs baseline: 3.5884x; 1.0258x over previous
#include <cuda_runtime.h>
#include <cstdint>

// ---------------------------------------------------------------------------
// 2-layer ConvLSTM2D, tf32 mma.sync + ldmatrix.x4 + cp.async double buffering.
// CTA = 128 pixels x 256 gates, 512 threads / 16 warps (4m x 4n), warp tile
// 32x64 gate-interleaved.  LSTM pointwise fused in registers.  B pre-
// transposed [n][k]/tf32-rounded; h / seq0 stored tf32-rounded.
// State buffers selected INSIDE device code.
// (Identical to the round-12 submission, which failed on infra before run.)
// ---------------------------------------------------------------------------

#define HWPIX 4096
#define NPIX 32768
#define HC_ELEMS (NPIX * 64)
#define SEQ_ELEMS (10 * HC_ELEMS)
#define IMGF 9216                    // floats per B image: 256 n-rows x 36 k

__device__ float g_h0a[HC_ELEMS];
__device__ float g_h0b[HC_ELEMS];
__device__ float g_h1a[HC_ELEMS];
__device__ float g_h1b[HC_ELEMS];
__device__ float g_c0[HC_ELEMS];
__device__ float g_c1[HC_ELEMS];
__device__ float g_seq0[SEQ_ELEMS];  // (b,t,y,x,f), tf32-rounded
__device__ float g_Bw0[18 * IMGF];   // layer0 B images [n][36]
__device__ float g_Bw1[36 * IMGF];   // layer1 B images [n][36]

// ------------------------------ helpers ------------------------------------
__device__ __forceinline__ uint32_t smem_u32(const void* p) {
    uint32_t a;
    asm("{ .reg .u64 t; cvta.to.shared.u64 t, %1; cvt.u32.u64 %0, t; }"
        : "=r"(a) : "l"(p));
    return a;
}
__device__ __forceinline__ float to_tf32(float x) {
    float r; asm("cvt.rna.tf32.f32 %0, %1;" : "=f"(r) : "f"(x)); return r;
}
__device__ __forceinline__ float hsig(float v) {
    return fminf(fmaxf(0.2f * v + 0.5f, 0.f), 1.f);
}
__device__ __forceinline__ void mma_tf32u(float c[4], const uint32_t a[4],
                                          uint32_t b0, uint32_t b1) {
    asm volatile(
        "mma.sync.aligned.m16n8k8.row.col.f32.tf32.tf32.f32 "
        "{%0,%1,%2,%3}, {%4,%5,%6,%7}, {%8,%9}, {%0,%1,%2,%3};"
        : "+f"(c[0]), "+f"(c[1]), "+f"(c[2]), "+f"(c[3])
        : "r"(a[0]), "r"(a[1]), "r"(a[2]), "r"(a[3]), "r"(b0), "r"(b1));
}
#define LDSM4(r0, r1, r2, r3, addr) \
    asm volatile("ldmatrix.sync.aligned.m8n8.x4.shared.b16 {%0,%1,%2,%3}, [%4];" \
        : "=r"(r0), "=r"(r1), "=r"(r2), "=r"(r3) : "r"(addr))
#define CP_COMMIT() asm volatile("cp.async.commit_group;" ::: "memory")
#define CP_WAIT1()  asm volatile("cp.async.wait_group 1;" ::: "memory")

// ------------------------------ small kernels ------------------------------
__global__ void zero_state_kernel() {
    int i = blockIdx.x * 256 + threadIdx.x;
    g_h0a[i] = 0.f; g_h1a[i] = 0.f; g_c0[i] = 0.f; g_c1[i] = 0.f;
}

// B images: transposed [n 256][k 36 (pad, 32 valid)] per (tap,kc) chunk.
__global__ void prep_weights(const float* __restrict__ rk0,
                             const float* __restrict__ k1,
                             const float* __restrict__ rk1) {
    const int i = blockIdx.x * 256 + threadIdx.x;   // < 54*IMGF
    const int img = i / IMGF;
    const int e = i % IMGF;
    const int n = e / 36, k = e % 36;
    float v = 0.f; float* dst;
    if (img < 18) {
        const int tap = img >> 1, kc = img & 1;
        if (k < 32) v = rk0[(tap * 64 + kc * 32 + k) * 256 + n];
        dst = g_Bw0 + img * IMGF;
    } else {
        const int c = img - 18, tap = c >> 1, kc = c & 1;
        if (k < 32)
            v = (tap < 9) ? k1[(tap * 64 + kc * 32 + k) * 256 + n]
                          : rk1[((tap - 9) * 64 + kc * 32 + k) * 256 + n];
        dst = g_Bw1 + c * IMGF;
    }
    dst[n * 36 + k] = to_tf32(v);
}

__global__ void copy_out_kernel(float* __restrict__ out, int pp) {
    const int i = blockIdx.x * 256 + threadIdx.x;
    const int r = i >> 21;
    const int local = i & (HC_ELEMS - 1);
    float v;
    if      (r == 0) v = pp ? g_h0a[local] : g_h0b[local];
    else if (r == 1) v = g_c0[local];
    else if (r == 2) v = pp ? g_h1a[local] : g_h1b[local];
    else             v = g_c1[local];
    out[i] = v;
}

// ------------------------------ main kernel --------------------------------
// smem: A ping/pong 128x36 f32 (18432B) at 0/18432,
//       B ping/pong 256x36 f32 (36864B) at 36864/73728.  Total 110592B.
template<int LAYER>
__global__ __launch_bounds__(512, 1)
void convlstm_step(int t, int pp,
                   const float* __restrict__ bias,
                   const float* __restrict__ xin,
                   const float* __restrict__ k0g)
{
    const float* hprev; float* hnext; float* cbuf;
    if (LAYER == 0) {
        hprev = pp ? g_h0b : g_h0a;
        hnext = pp ? g_h0a : g_h0b;
        cbuf  = g_c0;
    } else {
        hprev = pp ? g_h1b : g_h1a;
        hnext = pp ? g_h1a : g_h1b;
        cbuf  = g_c1;
    }

    extern __shared__ float smem[];
    const uint32_t sbase = smem_u32(smem);
    const uint32_t sA[2] = { sbase, sbase + 18432u };
    const uint32_t sB[2] = { sbase + 36864u, sbase + 73728u };

    const int tid = threadIdx.x;
    const int lane = tid & 31, wid = tid >> 5;        // wid 0..15
    const int lr = lane >> 2, lc = lane & 3;
    const int wm = (wid >> 2) * 32;          // warp m-base: 0,32,64,96
    const int wn16 = (wid & 3) * 16;         // warp n-base within each gate
    const int bm = blockIdx.x;               // 0..255

    // A-loader mapping: 4 threads per pixel row, 8 f32 (32B) each
    const int rowA = tid >> 2;               // 0..127
    const int partA = (tid & 3) * 8;         // 0,8,16,24
    const int m = bm * 128 + rowA;
    const int ab = m >> 12, ay = (m >> 6) & 63, ax = m & 63;

    const float* BW = (LAYER == 0) ? g_Bw0 : g_Bw1;
    const int NCH = (LAYER == 0) ? 18 : 36;

    float acc[2][8][4];
    #pragma unroll
    for (int i = 0; i < 2; i++)
        #pragma unroll
        for (int j = 0; j < 8; j++)
            #pragma unroll
            for (int r = 0; r < 4; r++) acc[i][j][r] = 0.f;

    // ---- async loaders ----
    auto issueB = [&](int ci, int buf) {
        const char* src = (const char*)(BW + ci * IMGF);
        const uint32_t dstb = sB[buf];
        #pragma unroll
        for (int q = 0; q < 5; q++) {
            const int c16 = tid + q * 512;            // 16B chunk index
            if (c16 < 2304) {
                const int idx = c16 * 16;
                asm volatile("cp.async.ca.shared.global [%0], [%1], 16;"
                    :: "r"(dstb + idx), "l"(src + idx) : "memory");
            }
        }
    };
    auto issueA = [&](int ci, int buf) {
        int tap = ci >> 1;
        const int kc = ci & 1;
        const float* src; long long bstr;
        if (LAYER == 1 && tap < 9) {
            src = g_seq0 + (long long)t * (HWPIX * 64);
            bstr = (long long)10 * HWPIX * 64;
        } else {
            if (LAYER == 1) tap -= 9;
            src = hprev; bstr = (long long)HWPIX * 64;
        }
        const int dy = tap / 3 - 1, dx = tap % 3 - 1;
        const int yy = ay + dy, xx = ax + dx;
        const bool inb = ((unsigned)yy < 64u) && ((unsigned)xx < 64u);
        const int pr = inb ? 16 : 0;
        const int yc = min(max(yy, 0), 63), xc = min(max(xx, 0), 63);
        const char* ap = (const char*)(src + (long long)ab * bstr
                        + ((yc << 6) + xc) * 64 + kc * 32 + partA);
        const uint32_t dst = sA[buf] + rowA * 144 + partA * 4;
        #pragma unroll
        for (int q = 0; q < 2; q++)
            asm volatile("cp.async.ca.shared.global [%0], [%1], 16, %2;"
                :: "r"(dst + q * 16), "l"(ap + q * 16), "r"(pr) : "memory");
    };

    issueA(0, 0);
    issueB(0, 0);
    CP_COMMIT();

    // ---- main loop ----
    const int r16 = lane & 15;
    const int hi = (lane >> 4) * 16;
    #pragma unroll 1
    for (int ci = 0; ci < NCH; ci++) {
        const int buf = ci & 1;
        if (ci + 1 < NCH) { issueA(ci + 1, buf ^ 1); issueB(ci + 1, buf ^ 1); }
        CP_COMMIT();
        CP_WAIT1();
        __syncthreads();

        const uint32_t abase = sA[buf], bbase = sB[buf];
        #pragma unroll
        for (int ks = 0; ks < 4; ks++) {
            uint32_t a[2][4], b[4][4];
            #pragma unroll
            for (int i = 0; i < 2; i++) {
                const uint32_t ad = abase + (wm + i * 16 + r16) * 144
                                  + ks * 32 + hi;
                LDSM4(a[i][0], a[i][1], a[i][2], a[i][3], ad);
            }
            #pragma unroll
            for (int g = 0; g < 4; g++) {
                const uint32_t bd = bbase + (g * 64 + wn16 + r16) * 144
                                  + ks * 32 + hi;
                LDSM4(b[g][0], b[g][1], b[g][2], b[g][3], bd);
            }
            #pragma unroll
            for (int i = 0; i < 2; i++)
                #pragma unroll
                for (int g = 0; g < 4; g++) {
                    mma_tf32u(acc[i][g * 2 + 0], a[i], b[g][0], b[g][2]);
                    mma_tf32u(acc[i][g * 2 + 1], a[i], b[g][1], b[g][3]);
                }
        }
        __syncthreads();
    }

    // ---- fused LSTM epilogue: all 4 gates in-register per thread ----
    #pragma unroll
    for (int i = 0; i < 2; i++) {
        #pragma unroll
        for (int rp = 0; rp < 2; rp++) {
            const int pix = bm * 128 + wm + i * 16 + lr + rp * 8;
            const int r0 = rp * 2;
            float xv[9];
            if (LAYER == 0) {
                const int bb = pix >> 12, y = (pix >> 6) & 63, x = pix & 63;
                #pragma unroll
                for (int tap = 0; tap < 9; tap++) {
                    const int dy = tap / 3 - 1, dx = tap % 3 - 1;
                    const int yy = y + dy, xx = x + dx;
                    xv[tap] = (((unsigned)yy < 64u) && ((unsigned)xx < 64u))
                        ? __ldg(&xin[(long long)(bb * 10 + t) * HWPIX
                                     + yy * 64 + xx])
                        : 0.f;
                }
            }
            #pragma unroll
            for (int jj = 0; jj < 2; jj++) {
                const int f = wn16 + jj * 8 + 2 * lc;
                #pragma unroll
                for (int u = 0; u < 2; u++) {
                    float zi = acc[i][jj][r0 + u]     + __ldg(&bias[f + u]);
                    float zf = acc[i][2 + jj][r0 + u] + __ldg(&bias[64 + f + u]);
                    float zg = acc[i][4 + jj][r0 + u] + __ldg(&bias[128 + f + u]);
                    float zo = acc[i][6 + jj][r0 + u] + __ldg(&bias[192 + f + u]);
                    if (LAYER == 0) {
                        #pragma unroll
                        for (int tap = 0; tap < 9; tap++) {
                            const float kx = xv[tap];
                            zi = fmaf(kx, __ldg(&k0g[tap * 256 + f + u]), zi);
                            zf = fmaf(kx, __ldg(&k0g[tap * 256 + 64 + f + u]), zf);
                            zg = fmaf(kx, __ldg(&k0g[tap * 256 + 128 + f + u]), zg);
                            zo = fmaf(kx, __ldg(&k0g[tap * 256 + 192 + f + u]), zo);
                        }
                    }
                    const long long base = (long long)pix * 64 + f + u;
                    const float cp = cbuf[base];
                    const float cn = hsig(zf) * cp + hsig(zi) * tanhf(zg);
                    const float hn = hsig(zo) * tanhf(cn);
                    cbuf[base] = cn;
                    const float hr = to_tf32(hn);
                    hnext[base] = hr;
                    if (LAYER == 0) {
                        g_seq0[((long long)((pix >> 12) * 10 + t) * HWPIX
                                + (pix & 4095)) * 64 + f + u] = hr;
                    }
                }
            }
        }
    }
}

// ---------------------------------------------------------------------------
extern "C" void kernel_launch(void* const* d_in, const int* in_sizes, int n_in,
                              void* d_out, int out_size)
{
    const float* x   = (const float*)d_in[0];
    const float* k0  = (const float*)d_in[1];
    const float* rk0 = (const float*)d_in[2];
    const float* b0  = (const float*)d_in[3];
    const float* k1  = (const float*)d_in[4];
    const float* rk1 = (const float*)d_in[5];
    const float* b1  = (const float*)d_in[6];
    float* out = (float*)d_out;

    cudaFuncSetAttribute(convlstm_step<0>,
                         cudaFuncAttributeMaxDynamicSharedMemorySize, 110592);
    cudaFuncSetAttribute(convlstm_step<1>,
                         cudaFuncAttributeMaxDynamicSharedMemorySize, 110592);

    zero_state_kernel<<<HC_ELEMS / 256, 256>>>();
    prep_weights<<<(54 * IMGF) / 256, 256>>>(rk0, k1, rk1);

    for (int t = 0; t < 10; ++t) {
        const int pp = t & 1;
        convlstm_step<0><<<256, 512, 110592>>>(t, pp, b0, x, k0);
        convlstm_step<1><<<256, 512, 110592>>>(t, pp, b1, nullptr, nullptr);
    }

    // t=9 wrote with pp=1 -> "a" buffers hold final h
    copy_out_kernel<<<(4 * HC_ELEMS) / 256, 256>>>(out, 1);
}

// round 14
// speedup vs baseline: 3.6507x; 1.0174x over previous
#include <cuda_runtime.h>
#include <cstdint>

// ---------------------------------------------------------------------------
// 2-layer ConvLSTM2D, tf32 mma.sync + ldmatrix.x4 + cp.async 3-stage ring.
// CTA = 128 pixels x 256 gates, 512 threads / 16 warps (4m x 4n), warp tile
// 32x64 gate-interleaved.  One __syncthreads per chunk; tap geometry hoisted.
// LSTM pointwise fused in registers.  B pre-transposed [n][k]/tf32-rounded;
// h / seq0 stored tf32-rounded.  State buffers selected INSIDE device code.
// ---------------------------------------------------------------------------

#define HWPIX 4096
#define NPIX 32768
#define HC_ELEMS (NPIX * 64)
#define SEQ_ELEMS (10 * HC_ELEMS)
#define IMGF 9216                    // floats per B image: 256 n-rows x 36 k

__device__ float g_h0a[HC_ELEMS];
__device__ float g_h0b[HC_ELEMS];
__device__ float g_h1a[HC_ELEMS];
__device__ float g_h1b[HC_ELEMS];
__device__ float g_c0[HC_ELEMS];
__device__ float g_c1[HC_ELEMS];
__device__ float g_seq0[SEQ_ELEMS];  // (b,t,y,x,f), tf32-rounded
__device__ float g_Bw0[18 * IMGF];   // layer0 B images [n][36]
__device__ float g_Bw1[36 * IMGF];   // layer1 B images [n][36]

// ------------------------------ helpers ------------------------------------
__device__ __forceinline__ uint32_t smem_u32(const void* p) {
    uint32_t a;
    asm("{ .reg .u64 t; cvta.to.shared.u64 t, %1; cvt.u32.u64 %0, t; }"
        : "=r"(a) : "l"(p));
    return a;
}
__device__ __forceinline__ float to_tf32(float x) {
    float r; asm("cvt.rna.tf32.f32 %0, %1;" : "=f"(r) : "f"(x)); return r;
}
__device__ __forceinline__ float hsig(float v) {
    return fminf(fmaxf(0.2f * v + 0.5f, 0.f), 1.f);
}
__device__ __forceinline__ void mma_tf32u(float c[4], const uint32_t a[4],
                                          uint32_t b0, uint32_t b1) {
    asm volatile(
        "mma.sync.aligned.m16n8k8.row.col.f32.tf32.tf32.f32 "
        "{%0,%1,%2,%3}, {%4,%5,%6,%7}, {%8,%9}, {%0,%1,%2,%3};"
        : "+f"(c[0]), "+f"(c[1]), "+f"(c[2]), "+f"(c[3])
        : "r"(a[0]), "r"(a[1]), "r"(a[2]), "r"(a[3]), "r"(b0), "r"(b1));
}
#define LDSM4(r0, r1, r2, r3, addr) \
    asm volatile("ldmatrix.sync.aligned.m8n8.x4.shared.b16 {%0,%1,%2,%3}, [%4];" \
        : "=r"(r0), "=r"(r1), "=r"(r2), "=r"(r3) : "r"(addr))
#define CP_COMMIT() asm volatile("cp.async.commit_group;" ::: "memory")
#define CP_WAIT0()  asm volatile("cp.async.wait_group 0;" ::: "memory")
#define CP_WAIT1g() asm volatile("cp.async.wait_group 1;" ::: "memory")

// ------------------------------ small kernels ------------------------------
__global__ void zero_state_kernel() {
    int i = blockIdx.x * 256 + threadIdx.x;
    g_h0a[i] = 0.f; g_h1a[i] = 0.f; g_c0[i] = 0.f; g_c1[i] = 0.f;
}

// B images: transposed [n 256][k 36 (pad, 32 valid)] per (tap,kc) chunk.
__global__ void prep_weights(const float* __restrict__ rk0,
                             const float* __restrict__ k1,
                             const float* __restrict__ rk1) {
    const int i = blockIdx.x * 256 + threadIdx.x;   // < 54*IMGF
    const int img = i / IMGF;
    const int e = i % IMGF;
    const int n = e / 36, k = e % 36;
    float v = 0.f; float* dst;
    if (img < 18) {
        const int tap = img >> 1, kc = img & 1;
        if (k < 32) v = rk0[(tap * 64 + kc * 32 + k) * 256 + n];
        dst = g_Bw0 + img * IMGF;
    } else {
        const int c = img - 18, tap = c >> 1, kc = c & 1;
        if (k < 32)
            v = (tap < 9) ? k1[(tap * 64 + kc * 32 + k) * 256 + n]
                          : rk1[((tap - 9) * 64 + kc * 32 + k) * 256 + n];
        dst = g_Bw1 + c * IMGF;
    }
    dst[n * 36 + k] = to_tf32(v);
}

__global__ void copy_out_kernel(float* __restrict__ out, int pp) {
    const int i = blockIdx.x * 256 + threadIdx.x;
    const int r = i >> 21;
    const int local = i & (HC_ELEMS - 1);
    float v;
    if      (r == 0) v = pp ? g_h0a[local] : g_h0b[local];
    else if (r == 1) v = g_c0[local];
    else if (r == 2) v = pp ? g_h1a[local] : g_h1b[local];
    else             v = g_c1[local];
    out[i] = v;
}

// ------------------------------ main kernel --------------------------------
// smem ring (3 stages): A 128x36 f32 (18432B) at s*18432,
//                       B 256x36 f32 (36864B) at 55296 + s*36864.
// Total 165888B.
template<int LAYER>
__global__ __launch_bounds__(512, 1)
void convlstm_step(int t, int pp,
                   const float* __restrict__ bias,
                   const float* __restrict__ xin,
                   const float* __restrict__ k0g)
{
    const float* hprev; float* hnext; float* cbuf;
    if (LAYER == 0) {
        hprev = pp ? g_h0b : g_h0a;
        hnext = pp ? g_h0a : g_h0b;
        cbuf  = g_c0;
    } else {
        hprev = pp ? g_h1b : g_h1a;
        hnext = pp ? g_h1a : g_h1b;
        cbuf  = g_c1;
    }

    extern __shared__ float smem[];
    const uint32_t sbase = smem_u32(smem);

    const int tid = threadIdx.x;
    const int lane = tid & 31, wid = tid >> 5;        // wid 0..15
    const int lr = lane >> 2, lc = lane & 3;
    const int wm = (wid >> 2) * 32;          // warp m-base: 0,32,64,96
    const int wn16 = (wid & 3) * 16;         // warp n-base within each gate
    const int bm = blockIdx.x;               // 0..255

    // A-loader mapping: 4 threads per pixel row, 8 f32 (32B) each
    const int rowA = tid >> 2;               // 0..127
    const int partA = (tid & 3) * 8;         // 0,8,16,24
    const int m = bm * 128 + rowA;
    const int ab = m >> 12, ay = (m >> 6) & 63, ax = m & 63;

    // ---- hoisted tap geometry: offsets + in-bounds mask (computed once) ----
    int off9[9];
    int inbm = 0;
    #pragma unroll
    for (int tap = 0; tap < 9; tap++) {
        const int dy = tap / 3 - 1, dx = tap % 3 - 1;
        const int yy = ay + dy, xx = ax + dx;
        if (((unsigned)yy < 64u) && ((unsigned)xx < 64u)) inbm |= (1 << tap);
        const int yc = min(max(yy, 0), 63), xc = min(max(xx, 0), 63);
        off9[tap] = ((yc << 6) + xc) * 64;
    }
    const float* hbase = hprev + (long long)ab * (HWPIX * 64) + partA;
    const float* sbase_p = (LAYER == 1)
        ? g_seq0 + (long long)(ab * 10 + t) * (HWPIX * 64) + partA
        : nullptr;

    const float* BW = (LAYER == 0) ? g_Bw0 : g_Bw1;
    const int NCH = (LAYER == 0) ? 18 : 36;

    float acc[2][8][4];
    #pragma unroll
    for (int i = 0; i < 2; i++)
        #pragma unroll
        for (int j = 0; j < 8; j++)
            #pragma unroll
            for (int r = 0; r < 4; r++) acc[i][j][r] = 0.f;

    // ---- async loaders ----
    auto issueB = [&](int ci, int st) {
        const char* src = (const char*)(BW + ci * IMGF);
        const uint32_t dstb = sbase + 55296u + st * 36864u;
        #pragma unroll
        for (int q = 0; q < 5; q++) {
            const int c16 = tid + q * 512;            // 16B chunk index
            if (c16 < 2304) {
                const int idx = c16 * 16;
                asm volatile("cp.async.ca.shared.global [%0], [%1], 16;"
                    :: "r"(dstb + idx), "l"(src + idx) : "memory");
            }
        }
    };
    auto issueA = [&](int ci, int st) {
        int tap = ci >> 1;
        const int kc = ci & 1;
        const float* base;
        if (LAYER == 1) {
            if (tap < 9) base = sbase_p;
            else { tap -= 9; base = hbase; }
        } else {
            base = hbase;
        }
        const int pr = ((inbm >> tap) & 1) ? 16 : 0;
        const char* ap = (const char*)(base + off9[tap] + kc * 32);
        const uint32_t dst = sbase + st * 18432u + rowA * 144 + partA * 4;
        #pragma unroll
        for (int q = 0; q < 2; q++)
            asm volatile("cp.async.ca.shared.global [%0], [%1], 16, %2;"
                :: "r"(dst + q * 16), "l"(ap + q * 16), "r"(pr) : "memory");
    };

    // prologue: chunks 0 and 1 into stages 0 and 1
    issueA(0, 0); issueB(0, 0); CP_COMMIT();
    issueA(1, 1); issueB(1, 1); CP_COMMIT();

    // ---- main loop: one barrier per chunk ----
    const int r16 = lane & 15;
    const int hi = (lane >> 4) * 16;
    int st = 0, stn = 2;                      // compute stage, next-issue stage
    #pragma unroll 1
    for (int ci = 0; ci < NCH; ci++) {
        if (ci == NCH - 1) { CP_WAIT0(); } else { CP_WAIT1g(); }
        __syncthreads();
        if (ci + 2 < NCH) {
            issueA(ci + 2, stn); issueB(ci + 2, stn);
            CP_COMMIT();
        }

        const uint32_t abase = sbase + st * 18432u;
        const uint32_t bbase = sbase + 55296u + st * 36864u;
        #pragma unroll
        for (int ks = 0; ks < 4; ks++) {
            uint32_t a[2][4], b[4][4];
            #pragma unroll
            for (int i = 0; i < 2; i++) {
                const uint32_t ad = abase + (wm + i * 16 + r16) * 144
                                  + ks * 32 + hi;
                LDSM4(a[i][0], a[i][1], a[i][2], a[i][3], ad);
            }
            #pragma unroll
            for (int g = 0; g < 4; g++) {
                const uint32_t bd = bbase + (g * 64 + wn16 + r16) * 144
                                  + ks * 32 + hi;
                LDSM4(b[g][0], b[g][1], b[g][2], b[g][3], bd);
            }
            #pragma unroll
            for (int i = 0; i < 2; i++)
                #pragma unroll
                for (int g = 0; g < 4; g++) {
                    mma_tf32u(acc[i][g * 2 + 0], a[i], b[g][0], b[g][2]);
                    mma_tf32u(acc[i][g * 2 + 1], a[i], b[g][1], b[g][3]);
                }
        }
        if (++st == 3) st = 0;
        if (++stn == 3) stn = 0;
    }

    // ---- fused LSTM epilogue: all 4 gates in-register per thread ----
    #pragma unroll
    for (int i = 0; i < 2; i++) {
        #pragma unroll
        for (int rp = 0; rp < 2; rp++) {
            const int pix = bm * 128 + wm + i * 16 + lr + rp * 8;
            const int r0 = rp * 2;
            float xv[9];
            if (LAYER == 0) {
                const int bb = pix >> 12, y = (pix >> 6) & 63, x = pix & 63;
                #pragma unroll
                for (int tap = 0; tap < 9; tap++) {
                    const int dy = tap / 3 - 1, dx = tap % 3 - 1;
                    const int yy = y + dy, xx = x + dx;
                    xv[tap] = (((unsigned)yy < 64u) && ((unsigned)xx < 64u))
                        ? __ldg(&xin[(long long)(bb * 10 + t) * HWPIX
                                     + yy * 64 + xx])
                        : 0.f;
                }
            }
            #pragma unroll
            for (int jj = 0; jj < 2; jj++) {
                const int f = wn16 + jj * 8 + 2 * lc;
                #pragma unroll
                for (int u = 0; u < 2; u++) {
                    float zi = acc[i][jj][r0 + u]     + __ldg(&bias[f + u]);
                    float zf = acc[i][2 + jj][r0 + u] + __ldg(&bias[64 + f + u]);
                    float zg = acc[i][4 + jj][r0 + u] + __ldg(&bias[128 + f + u]);
                    float zo = acc[i][6 + jj][r0 + u] + __ldg(&bias[192 + f + u]);
                    if (LAYER == 0) {
                        #pragma unroll
                        for (int tap = 0; tap < 9; tap++) {
                            const float kx = xv[tap];
                            zi = fmaf(kx, __ldg(&k0g[tap * 256 + f + u]), zi);
                            zf = fmaf(kx, __ldg(&k0g[tap * 256 + 64 + f + u]), zf);
                            zg = fmaf(kx, __ldg(&k0g[tap * 256 + 128 + f + u]), zg);
                            zo = fmaf(kx, __ldg(&k0g[tap * 256 + 192 + f + u]), zo);
                        }
                    }
                    const long long base = (long long)pix * 64 + f + u;
                    const float cp = cbuf[base];
                    const float cn = hsig(zf) * cp + hsig(zi) * tanhf(zg);
                    const float hn = hsig(zo) * tanhf(cn);
                    cbuf[base] = cn;
                    const float hr = to_tf32(hn);
                    hnext[base] = hr;
                    if (LAYER == 0) {
                        g_seq0[((long long)((pix >> 12) * 10 + t) * HWPIX
                                + (pix & 4095)) * 64 + f + u] = hr;
                    }
                }
            }
        }
    }
}

// ---------------------------------------------------------------------------
extern "C" void kernel_launch(void* const* d_in, const int* in_sizes, int n_in,
                              void* d_out, int out_size)
{
    const float* x   = (const float*)d_in[0];
    const float* k0  = (const float*)d_in[1];
    const float* rk0 = (const float*)d_in[2];
    const float* b0  = (const float*)d_in[3];
    const float* k1  = (const float*)d_in[4];
    const float* rk1 = (const float*)d_in[5];
    const float* b1  = (const float*)d_in[6];
    float* out = (float*)d_out;

    cudaFuncSetAttribute(convlstm_step<0>,
                         cudaFuncAttributeMaxDynamicSharedMemorySize, 165888);
    cudaFuncSetAttribute(convlstm_step<1>,
                         cudaFuncAttributeMaxDynamicSharedMemorySize, 165888);

    zero_state_kernel<<<HC_ELEMS / 256, 256>>>();
    prep_weights<<<(54 * IMGF) / 256, 256>>>(rk0, k1, rk1);

    for (int t = 0; t < 10; ++t) {
        const int pp = t & 1;
        convlstm_step<0><<<256, 512, 165888>>>(t, pp, b0, x, k0);
        convlstm_step<1><<<256, 512, 165888>>>(t, pp, b1, nullptr, nullptr);
    }

    // t=9 wrote with pp=1 -> "a" buffers hold final h
    copy_out_kernel<<<(4 * HC_ELEMS) / 256, 256>>>(out, 1);
}

// round 15
// speedup vs baseline: 3.7269x; 1.0209x over previous
#include <cuda_runtime.h>
#include <cstdint>

// ---------------------------------------------------------------------------
// 2-layer ConvLSTM2D, tf32 mma.sync + ldmatrix.x4.  B tiles fetched with
// cp.async.bulk (TMA bulk copy, zero SM issue cost) + mbarrier completion;
// A gather via regular cp.async.  3-stage smem ring, one __syncthreads per
// chunk.  CTA = 128 pixels x 256 gates, 512 threads / 16 warps (4m x 4n).
// LSTM pointwise fused in registers.  State buffers selected in device code.
// ---------------------------------------------------------------------------

#define HWPIX 4096
#define NPIX 32768
#define HC_ELEMS (NPIX * 64)
#define SEQ_ELEMS (10 * HC_ELEMS)
#define IMGF 9216                    // floats per B image: 256 n-rows x 36 k
#define BIMG_BYTES 36864

__device__ float g_h0a[HC_ELEMS];
__device__ float g_h0b[HC_ELEMS];
__device__ float g_h1a[HC_ELEMS];
__device__ float g_h1b[HC_ELEMS];
__device__ float g_c0[HC_ELEMS];
__device__ float g_c1[HC_ELEMS];
__device__ float g_seq0[SEQ_ELEMS];  // (b,t,y,x,f), tf32-rounded
__device__ float g_Bw0[18 * IMGF];   // layer0 B images [n][36]
__device__ float g_Bw1[36 * IMGF];   // layer1 B images [n][36]

// ------------------------------ helpers ------------------------------------
__device__ __forceinline__ uint32_t smem_u32(const void* p) {
    uint32_t a;
    asm("{ .reg .u64 t; cvta.to.shared.u64 t, %1; cvt.u32.u64 %0, t; }"
        : "=r"(a) : "l"(p));
    return a;
}
__device__ __forceinline__ float to_tf32(float x) {
    float r; asm("cvt.rna.tf32.f32 %0, %1;" : "=f"(r) : "f"(x)); return r;
}
__device__ __forceinline__ float hsig(float v) {
    return fminf(fmaxf(0.2f * v + 0.5f, 0.f), 1.f);
}
__device__ __forceinline__ void mma_tf32u(float c[4], const uint32_t a[4],
                                          uint32_t b0, uint32_t b1) {
    asm volatile(
        "mma.sync.aligned.m16n8k8.row.col.f32.tf32.tf32.f32 "
        "{%0,%1,%2,%3}, {%4,%5,%6,%7}, {%8,%9}, {%0,%1,%2,%3};"
        : "+f"(c[0]), "+f"(c[1]), "+f"(c[2]), "+f"(c[3])
        : "r"(a[0]), "r"(a[1]), "r"(a[2]), "r"(a[3]), "r"(b0), "r"(b1));
}
#define LDSM4(r0, r1, r2, r3, addr) \
    asm volatile("ldmatrix.sync.aligned.m8n8.x4.shared.b16 {%0,%1,%2,%3}, [%4];" \
        : "=r"(r0), "=r"(r1), "=r"(r2), "=r"(r3) : "r"(addr))
#define CP_COMMIT() asm volatile("cp.async.commit_group;" ::: "memory")
#define CP_WAIT0()  asm volatile("cp.async.wait_group 0;" ::: "memory")
#define CP_WAIT1g() asm volatile("cp.async.wait_group 1;" ::: "memory")
#define MB_INIT(mb, n) asm volatile("mbarrier.init.shared.b64 [%0], %1;" \
    :: "r"(mb), "r"(n) : "memory")

__device__ __forceinline__ void mb_wait(uint32_t mb, uint32_t parity) {
    uint32_t done;
    asm volatile("{\n\t.reg .pred p;\n\t"
        "mbarrier.try_wait.parity.acquire.cta.shared::cta.b64 p, [%1], %2;\n\t"
        "selp.b32 %0, 1, 0, p;\n\t}" : "=r"(done) : "r"(mb), "r"(parity) : "memory");
    if (!done) {
        asm volatile("{\n\t.reg .pred P1;\n\t"
            "WL_%=:\n\t"
            "mbarrier.try_wait.parity.acquire.cta.shared::cta.b64 P1, [%0], %1, 0x989680;\n\t"
            "@P1 bra.uni WD_%=;\n\t"
            "bra.uni WL_%=;\n\t"
            "WD_%=:\n\t}" :: "r"(mb), "r"(parity) : "memory");
    }
}

// ------------------------------ small kernels ------------------------------
__global__ void zero_state_kernel() {
    int i = blockIdx.x * 256 + threadIdx.x;
    g_h0a[i] = 0.f; g_h1a[i] = 0.f; g_c0[i] = 0.f; g_c1[i] = 0.f;
}

// B images: transposed [n 256][k 36 (pad, 32 valid)] per (tap,kc) chunk.
__global__ void prep_weights(const float* __restrict__ rk0,
                             const float* __restrict__ k1,
                             const float* __restrict__ rk1) {
    const int i = blockIdx.x * 256 + threadIdx.x;   // < 54*IMGF
    const int img = i / IMGF;
    const int e = i % IMGF;
    const int n = e / 36, k = e % 36;
    float v = 0.f; float* dst;
    if (img < 18) {
        const int tap = img >> 1, kc = img & 1;
        if (k < 32) v = rk0[(tap * 64 + kc * 32 + k) * 256 + n];
        dst = g_Bw0 + img * IMGF;
    } else {
        const int c = img - 18, tap = c >> 1, kc = c & 1;
        if (k < 32)
            v = (tap < 9) ? k1[(tap * 64 + kc * 32 + k) * 256 + n]
                          : rk1[((tap - 9) * 64 + kc * 32 + k) * 256 + n];
        dst = g_Bw1 + c * IMGF;
    }
    dst[n * 36 + k] = to_tf32(v);
}

__global__ void copy_out_kernel(float* __restrict__ out, int pp) {
    const int i = blockIdx.x * 256 + threadIdx.x;
    const int r = i >> 21;
    const int local = i & (HC_ELEMS - 1);
    float v;
    if      (r == 0) v = pp ? g_h0a[local] : g_h0b[local];
    else if (r == 1) v = g_c0[local];
    else if (r == 2) v = pp ? g_h1a[local] : g_h1b[local];
    else             v = g_c1[local];
    out[i] = v;
}

// ------------------------------ main kernel --------------------------------
// smem ring (3 stages): A 128x36 f32 (18432B) at s*18432,
//                       B 256x36 f32 (36864B) at 55296 + s*36864,
//                       3 mbarriers at 165888.  Total 165952B.
template<int LAYER>
__global__ __launch_bounds__(512, 1)
void convlstm_step(int t, int pp,
                   const float* __restrict__ bias,
                   const float* __restrict__ xin,
                   const float* __restrict__ k0g)
{
    const float* hprev; float* hnext; float* cbuf;
    if (LAYER == 0) {
        hprev = pp ? g_h0b : g_h0a;
        hnext = pp ? g_h0a : g_h0b;
        cbuf  = g_c0;
    } else {
        hprev = pp ? g_h1b : g_h1a;
        hnext = pp ? g_h1a : g_h1b;
        cbuf  = g_c1;
    }

    extern __shared__ float smem[];
    const uint32_t sbase = smem_u32(smem);
    const uint32_t mbb = sbase + 165888u;

    const int tid = threadIdx.x;
    const int lane = tid & 31, wid = tid >> 5;        // wid 0..15
    const int lr = lane >> 2, lc = lane & 3;
    const int wm = (wid >> 2) * 32;          // warp m-base: 0,32,64,96
    const int wn16 = (wid & 3) * 16;         // warp n-base within each gate
    const int bm = blockIdx.x;               // 0..255

    // A-loader mapping: 4 threads per pixel row, 8 f32 (32B) each
    const int rowA = tid >> 2;               // 0..127
    const int partA = (tid & 3) * 8;         // 0,8,16,24
    const int m = bm * 128 + rowA;
    const int ab = m >> 12, ay = (m >> 6) & 63, ax = m & 63;

    // ---- hoisted tap geometry ----
    int off9[9];
    int inbm = 0;
    #pragma unroll
    for (int tap = 0; tap < 9; tap++) {
        const int dy = tap / 3 - 1, dx = tap % 3 - 1;
        const int yy = ay + dy, xx = ax + dx;
        if (((unsigned)yy < 64u) && ((unsigned)xx < 64u)) inbm |= (1 << tap);
        const int yc = min(max(yy, 0), 63), xc = min(max(xx, 0), 63);
        off9[tap] = ((yc << 6) + xc) * 64;
    }
    const float* hbase = hprev + (long long)ab * (HWPIX * 64) + partA;
    const float* sbase_p = (LAYER == 1)
        ? g_seq0 + (long long)(ab * 10 + t) * (HWPIX * 64) + partA
        : nullptr;

    const float* BW = (LAYER == 0) ? g_Bw0 : g_Bw1;
    const int NCH = (LAYER == 0) ? 18 : 36;

    // ---- mbarrier init (one per ring stage) ----
    if (tid == 0) {
        MB_INIT(mbb + 0, 1);
        MB_INIT(mbb + 8, 1);
        MB_INIT(mbb + 16, 1);
    }
    __syncthreads();

    float acc[2][8][4];
    #pragma unroll
    for (int i = 0; i < 2; i++)
        #pragma unroll
        for (int j = 0; j < 8; j++)
            #pragma unroll
            for (int r = 0; r < 4; r++) acc[i][j][r] = 0.f;

    // ---- loaders ----
    auto issueB = [&](int ci, int st) {            // tid 0 only: TMA bulk copy
        if (tid == 0) {
            const uint32_t mb = mbb + st * 8;
            const char* src = (const char*)(BW + ci * IMGF);
            const uint32_t dst = sbase + 55296u + st * 36864u;
            asm volatile("mbarrier.arrive.expect_tx.shared.b64 _, [%0], %1;"
                :: "r"(mb), "r"((uint32_t)BIMG_BYTES) : "memory");
            asm volatile(
                "cp.async.bulk.shared::cta.global.mbarrier::complete_tx::bytes "
                "[%0], [%1], %2, [%3];"
                :: "r"(dst), "l"(src), "r"((uint32_t)BIMG_BYTES), "r"(mb)
                : "memory");
        }
    };
    auto issueA = [&](int ci, int st) {
        int tap = ci >> 1;
        const int kc = ci & 1;
        const float* base;
        if (LAYER == 1) {
            if (tap < 9) base = sbase_p;
            else { tap -= 9; base = hbase; }
        } else {
            base = hbase;
        }
        const int pr = ((inbm >> tap) & 1) ? 16 : 0;
        const char* ap = (const char*)(base + off9[tap] + kc * 32);
        const uint32_t dst = sbase + st * 18432u + rowA * 144 + partA * 4;
        #pragma unroll
        for (int q = 0; q < 2; q++)
            asm volatile("cp.async.ca.shared.global [%0], [%1], 16, %2;"
                :: "r"(dst + q * 16), "l"(ap + q * 16), "r"(pr) : "memory");
    };

    // prologue: chunks 0 and 1 into stages 0 and 1
    issueB(0, 0); issueA(0, 0); CP_COMMIT();
    issueB(1, 1); issueA(1, 1); CP_COMMIT();

    // ---- main loop: one barrier per chunk ----
    const int r16 = lane & 15;
    const int hi = (lane >> 4) * 16;
    int st = 0, stn = 2;                      // compute stage, next-issue stage
    #pragma unroll 1
    for (int ci = 0; ci < NCH; ci++) {
        if (ci == NCH - 1) { CP_WAIT0(); } else { CP_WAIT1g(); }
        mb_wait(mbb + st * 8, (unsigned)(ci / 3) & 1);
        __syncthreads();
        if (ci + 2 < NCH) {
            issueB(ci + 2, stn); issueA(ci + 2, stn);
            CP_COMMIT();
        }

        const uint32_t abase = sbase + st * 18432u;
        const uint32_t bbase = sbase + 55296u + st * 36864u;
        #pragma unroll
        for (int ks = 0; ks < 4; ks++) {
            uint32_t a[2][4], b[4][4];
            #pragma unroll
            for (int i = 0; i < 2; i++) {
                const uint32_t ad = abase + (wm + i * 16 + r16) * 144
                                  + ks * 32 + hi;
                LDSM4(a[i][0], a[i][1], a[i][2], a[i][3], ad);
            }
            #pragma unroll
            for (int g = 0; g < 4; g++) {
                const uint32_t bd = bbase + (g * 64 + wn16 + r16) * 144
                                  + ks * 32 + hi;
                LDSM4(b[g][0], b[g][1], b[g][2], b[g][3], bd);
            }
            #pragma unroll
            for (int i = 0; i < 2; i++)
                #pragma unroll
                for (int g = 0; g < 4; g++) {
                    mma_tf32u(acc[i][g * 2 + 0], a[i], b[g][0], b[g][2]);
                    mma_tf32u(acc[i][g * 2 + 1], a[i], b[g][1], b[g][3]);
                }
        }
        if (++st == 3) st = 0;
        if (++stn == 3) stn = 0;
    }

    // ---- fused LSTM epilogue: all 4 gates in-register per thread ----
    #pragma unroll
    for (int i = 0; i < 2; i++) {
        #pragma unroll
        for (int rp = 0; rp < 2; rp++) {
            const int pix = bm * 128 + wm + i * 16 + lr + rp * 8;
            const int r0 = rp * 2;
            float xv[9];
            if (LAYER == 0) {
                const int bb = pix >> 12, y = (pix >> 6) & 63, x = pix & 63;
                #pragma unroll
                for (int tap = 0; tap < 9; tap++) {
                    const int dy = tap / 3 - 1, dx = tap % 3 - 1;
                    const int yy = y + dy, xx = x + dx;
                    xv[tap] = (((unsigned)yy < 64u) && ((unsigned)xx < 64u))
                        ? __ldg(&xin[(long long)(bb * 10 + t) * HWPIX
                                     + yy * 64 + xx])
                        : 0.f;
                }
            }
            #pragma unroll
            for (int jj = 0; jj < 2; jj++) {
                const int f = wn16 + jj * 8 + 2 * lc;
                #pragma unroll
                for (int u = 0; u < 2; u++) {
                    float zi = acc[i][jj][r0 + u]     + __ldg(&bias[f + u]);
                    float zf = acc[i][2 + jj][r0 + u] + __ldg(&bias[64 + f + u]);
                    float zg = acc[i][4 + jj][r0 + u] + __ldg(&bias[128 + f + u]);
                    float zo = acc[i][6 + jj][r0 + u] + __ldg(&bias[192 + f + u]);
                    if (LAYER == 0) {
                        #pragma unroll
                        for (int tap = 0; tap < 9; tap++) {
                            const float kx = xv[tap];
                            zi = fmaf(kx, __ldg(&k0g[tap * 256 + f + u]), zi);
                            zf = fmaf(kx, __ldg(&k0g[tap * 256 + 64 + f + u]), zf);
                            zg = fmaf(kx, __ldg(&k0g[tap * 256 + 128 + f + u]), zg);
                            zo = fmaf(kx, __ldg(&k0g[tap * 256 + 192 + f + u]), zo);
                        }
                    }
                    const long long base = (long long)pix * 64 + f + u;
                    const float cp = cbuf[base];
                    const float cn = hsig(zf) * cp + hsig(zi) * tanhf(zg);
                    const float hn = hsig(zo) * tanhf(cn);
                    cbuf[base] = cn;
                    const float hr = to_tf32(hn);
                    hnext[base] = hr;
                    if (LAYER == 0) {
                        g_seq0[((long long)((pix >> 12) * 10 + t) * HWPIX
                                + (pix & 4095)) * 64 + f + u] = hr;
                    }
                }
            }
        }
    }
}

// ---------------------------------------------------------------------------
extern "C" void kernel_launch(void* const* d_in, const int* in_sizes, int n_in,
                              void* d_out, int out_size)
{
    const float* x   = (const float*)d_in[0];
    const float* k0  = (const float*)d_in[1];
    const float* rk0 = (const float*)d_in[2];
    const float* b0  = (const float*)d_in[3];
    const float* k1  = (const float*)d_in[4];
    const float* rk1 = (const float*)d_in[5];
    const float* b1  = (const float*)d_in[6];
    float* out = (float*)d_out;

    cudaFuncSetAttribute(convlstm_step<0>,
                         cudaFuncAttributeMaxDynamicSharedMemorySize, 165952);
    cudaFuncSetAttribute(convlstm_step<1>,
                         cudaFuncAttributeMaxDynamicSharedMemorySize, 165952);

    zero_state_kernel<<<HC_ELEMS / 256, 256>>>();
    prep_weights<<<(54 * IMGF) / 256, 256>>>(rk0, k1, rk1);

    for (int t = 0; t < 10; ++t) {
        const int pp = t & 1;
        convlstm_step<0><<<256, 512, 165952>>>(t, pp, b0, x, k0);
        convlstm_step<1><<<256, 512, 165952>>>(t, pp, b1, nullptr, nullptr);
    }

    // t=9 wrote with pp=1 -> "a" buffers hold final h
    copy_out_kernel<<<(4 * HC_ELEMS) / 256, 256>>>(out, 1);
}

// round 16
// speedup vs baseline: 5.7465x; 1.5419x over previous
#include <cuda_runtime.h>
#include <cuda_fp16.h>
#include <cstdint>

// ---------------------------------------------------------------------------
// 2-layer ConvLSTM2D, fp16 mma.sync m16n8k16 (fp32 accum) + ldmatrix.x4.
// One chunk = one 3x3 tap, K=64 channels.  B tiles via cp.async.bulk + mbarrier;
// A gather via cp.async.  3-stage smem ring, one __syncthreads per chunk.
// CTA = 128 pixels x 256 gates, 512 threads / 16 warps (4m x 4n).
// LSTM pointwise fused in registers (fp32).  h / seq0 / weights stored fp16
// (10-bit mantissa, same as tf32).  State buffers selected in device code.
// ---------------------------------------------------------------------------

#define HWPIX 4096
#define NPIX 32768
#define HC_ELEMS (NPIX * 64)
#define SEQ_ELEMS (10 * HC_ELEMS)
#define IMGH 18432                   // halfs per B image: 256 n-rows x 72 k(pad)
#define BIMG_BYTES 36864

__device__ __half g_h0a[HC_ELEMS];
__device__ __half g_h0b[HC_ELEMS];
__device__ __half g_h1a[HC_ELEMS];
__device__ __half g_h1b[HC_ELEMS];
__device__ float  g_c0[HC_ELEMS];
__device__ float  g_c1[HC_ELEMS];
__device__ __half g_seq0[SEQ_ELEMS]; // (b,t,y,x,f) fp16
__device__ __half g_Bh0[9 * IMGH];   // layer0 B images [n 256][72]
__device__ __half g_Bh1[18 * IMGH];  // layer1 B images [n 256][72]

// ------------------------------ helpers ------------------------------------
__device__ __forceinline__ uint32_t smem_u32(const void* p) {
    uint32_t a;
    asm("{ .reg .u64 t; cvta.to.shared.u64 t, %1; cvt.u32.u64 %0, t; }"
        : "=r"(a) : "l"(p));
    return a;
}
__device__ __forceinline__ float hsig(float v) {
    return fminf(fmaxf(0.2f * v + 0.5f, 0.f), 1.f);
}
__device__ __forceinline__ void mma_f16(float c[4], const uint32_t a[4],
                                        uint32_t b0, uint32_t b1) {
    asm volatile(
        "mma.sync.aligned.m16n8k16.row.col.f32.f16.f16.f32 "
        "{%0,%1,%2,%3}, {%4,%5,%6,%7}, {%8,%9}, {%0,%1,%2,%3};"
        : "+f"(c[0]), "+f"(c[1]), "+f"(c[2]), "+f"(c[3])
        : "r"(a[0]), "r"(a[1]), "r"(a[2]), "r"(a[3]), "r"(b0), "r"(b1));
}
#define LDSM4(r0, r1, r2, r3, addr) \
    asm volatile("ldmatrix.sync.aligned.m8n8.x4.shared.b16 {%0,%1,%2,%3}, [%4];" \
        : "=r"(r0), "=r"(r1), "=r"(r2), "=r"(r3) : "r"(addr))
#define CP_COMMIT() asm volatile("cp.async.commit_group;" ::: "memory")
#define CP_WAIT0()  asm volatile("cp.async.wait_group 0;" ::: "memory")
#define CP_WAIT1g() asm volatile("cp.async.wait_group 1;" ::: "memory")
#define MB_INIT(mb, n) asm volatile("mbarrier.init.shared.b64 [%0], %1;" \
    :: "r"(mb), "r"(n) : "memory")

__device__ __forceinline__ void mb_wait(uint32_t mb, uint32_t parity) {
    uint32_t done;
    asm volatile("{\n\t.reg .pred p;\n\t"
        "mbarrier.try_wait.parity.acquire.cta.shared::cta.b64 p, [%1], %2;\n\t"
        "selp.b32 %0, 1, 0, p;\n\t}" : "=r"(done) : "r"(mb), "r"(parity) : "memory");
    if (!done) {
        asm volatile("{\n\t.reg .pred P1;\n\t"
            "WL_%=:\n\t"
            "mbarrier.try_wait.parity.acquire.cta.shared::cta.b64 P1, [%0], %1, 0x989680;\n\t"
            "@P1 bra.uni WD_%=;\n\t"
            "bra.uni WL_%=;\n\t"
            "WD_%=:\n\t}" :: "r"(mb), "r"(parity) : "memory");
    }
}

// ------------------------------ small kernels ------------------------------
__global__ void zero_state_kernel() {
    int i = blockIdx.x * 256 + threadIdx.x;
    g_h0a[i] = __float2half(0.f); g_h1a[i] = __float2half(0.f);
    g_c0[i] = 0.f; g_c1[i] = 0.f;
}

// B images: transposed [n 256][k 72 (pad, 64 valid)] per tap, fp16.
__global__ void prep_weights(const float* __restrict__ rk0,
                             const float* __restrict__ k1,
                             const float* __restrict__ rk1) {
    const int i = blockIdx.x * 256 + threadIdx.x;   // < 27*IMGH
    const int img = i / IMGH;
    const int e = i % IMGH;
    const int n = e / 72, k = e % 72;
    float v = 0.f; __half* dst;
    if (img < 9) {
        if (k < 64) v = rk0[(img * 64 + k) * 256 + n];
        dst = g_Bh0 + img * IMGH;
    } else {
        const int c = img - 9;
        if (k < 64)
            v = (c < 9) ? k1[(c * 64 + k) * 256 + n]
                        : rk1[((c - 9) * 64 + k) * 256 + n];
        dst = g_Bh1 + c * IMGH;
    }
    dst[n * 72 + k] = __float2half(v);
}

__global__ void copy_out_kernel(float* __restrict__ out, int pp) {
    const int i = blockIdx.x * 256 + threadIdx.x;
    const int r = i >> 21;
    const int local = i & (HC_ELEMS - 1);
    float v;
    if      (r == 0) v = __half2float(pp ? g_h0a[local] : g_h0b[local]);
    else if (r == 1) v = g_c0[local];
    else if (r == 2) v = __half2float(pp ? g_h1a[local] : g_h1b[local]);
    else             v = g_c1[local];
    out[i] = v;
}

// ------------------------------ main kernel --------------------------------
// smem ring (3 stages): A 128x72 half (18432B) at s*18432,
//                       B 256x72 half (36864B) at 55296 + s*36864,
//                       3 mbarriers at 165888.  Total 165952B.
template<int LAYER>
__global__ __launch_bounds__(512, 1)
void convlstm_step(int t, int pp,
                   const float* __restrict__ bias,
                   const float* __restrict__ xin,
                   const float* __restrict__ k0g)
{
    const __half* hprev; __half* hnext; float* cbuf;
    if (LAYER == 0) {
        hprev = pp ? g_h0b : g_h0a;
        hnext = pp ? g_h0a : g_h0b;
        cbuf  = g_c0;
    } else {
        hprev = pp ? g_h1b : g_h1a;
        hnext = pp ? g_h1a : g_h1b;
        cbuf  = g_c1;
    }

    extern __shared__ float smem[];
    const uint32_t sbase = smem_u32(smem);
    const uint32_t mbb = sbase + 165888u;

    const int tid = threadIdx.x;
    const int lane = tid & 31, wid = tid >> 5;        // wid 0..15
    const int lr = lane >> 2, lc = lane & 3;
    const int wm = (wid >> 2) * 32;          // warp m-base: 0,32,64,96
    const int wn16 = (wid & 3) * 16;         // warp n-base within each gate
    const int bm = blockIdx.x;               // 0..255

    // A-loader mapping: 4 threads per pixel row, 16 halfs (32B) each
    const int rowA = tid >> 2;               // 0..127
    const int partA = (tid & 3) * 16;        // half offset: 0,16,32,48
    const int m = bm * 128 + rowA;
    const int ab = m >> 12, ay = (m >> 6) & 63, ax = m & 63;

    // ---- hoisted tap geometry ----
    int off9[9];
    int inbm = 0;
    #pragma unroll
    for (int tap = 0; tap < 9; tap++) {
        const int dy = tap / 3 - 1, dx = tap % 3 - 1;
        const int yy = ay + dy, xx = ax + dx;
        if (((unsigned)yy < 64u) && ((unsigned)xx < 64u)) inbm |= (1 << tap);
        const int yc = min(max(yy, 0), 63), xc = min(max(xx, 0), 63);
        off9[tap] = ((yc << 6) + xc) * 64;
    }
    const __half* hbase = hprev + (long long)ab * (HWPIX * 64) + partA;
    const __half* seqb = (LAYER == 1)
        ? g_seq0 + (long long)(ab * 10 + t) * (HWPIX * 64) + partA
        : nullptr;

    const __half* BW = (LAYER == 0) ? g_Bh0 : g_Bh1;
    const int NCH = (LAYER == 0) ? 9 : 18;

    // ---- mbarrier init (one per ring stage) ----
    if (tid == 0) {
        MB_INIT(mbb + 0, 1);
        MB_INIT(mbb + 8, 1);
        MB_INIT(mbb + 16, 1);
    }
    __syncthreads();

    float acc[2][8][4];
    #pragma unroll
    for (int i = 0; i < 2; i++)
        #pragma unroll
        for (int j = 0; j < 8; j++)
            #pragma unroll
            for (int r = 0; r < 4; r++) acc[i][j][r] = 0.f;

    // ---- loaders ----
    auto issueB = [&](int ci, int st) {            // tid 0 only: TMA bulk copy
        if (tid == 0) {
            const uint32_t mb = mbb + st * 8;
            const char* src = (const char*)(BW + ci * IMGH);
            const uint32_t dst = sbase + 55296u + st * 36864u;
            asm volatile("mbarrier.arrive.expect_tx.shared.b64 _, [%0], %1;"
                :: "r"(mb), "r"((uint32_t)BIMG_BYTES) : "memory");
            asm volatile(
                "cp.async.bulk.shared::cta.global.mbarrier::complete_tx::bytes "
                "[%0], [%1], %2, [%3];"
                :: "r"(dst), "l"(src), "r"((uint32_t)BIMG_BYTES), "r"(mb)
                : "memory");
        }
    };
    auto issueA = [&](int ci, int st) {
        const __half* base;
        int tap;
        if (LAYER == 1) {
            if (ci < 9) { base = seqb; tap = ci; }
            else        { base = hbase; tap = ci - 9; }
        } else {
            base = hbase; tap = ci;
        }
        const int pr = ((inbm >> tap) & 1) ? 16 : 0;
        const char* ap = (const char*)(base + off9[tap]);
        const uint32_t dst = sbase + st * 18432u + rowA * 144 + (tid & 3) * 32;
        #pragma unroll
        for (int q = 0; q < 2; q++)
            asm volatile("cp.async.ca.shared.global [%0], [%1], 16, %2;"
                :: "r"(dst + q * 16), "l"(ap + q * 16), "r"(pr) : "memory");
    };

    // prologue: chunks 0 and 1 into stages 0 and 1
    issueB(0, 0); issueA(0, 0); CP_COMMIT();
    issueB(1, 1); issueA(1, 1); CP_COMMIT();

    // ---- main loop: one chunk = one tap (K=64), one barrier per chunk ----
    const int r16 = lane & 15;
    const int hi = (lane >> 4) * 16;
    int st = 0, stn = 2;
    #pragma unroll 1
    for (int ci = 0; ci < NCH; ci++) {
        if (ci == NCH - 1) { CP_WAIT0(); } else { CP_WAIT1g(); }
        mb_wait(mbb + st * 8, (unsigned)(ci / 3) & 1);
        __syncthreads();
        if (ci + 2 < NCH) {
            issueB(ci + 2, stn); issueA(ci + 2, stn);
            CP_COMMIT();
        }

        const uint32_t abase = sbase + st * 18432u;
        const uint32_t bbase = sbase + 55296u + st * 36864u;
        #pragma unroll
        for (int ks = 0; ks < 4; ks++) {            // 4 x k16 = K 64
            uint32_t a[2][4], b[4][4];
            #pragma unroll
            for (int i = 0; i < 2; i++) {
                const uint32_t ad = abase + (wm + i * 16 + r16) * 144
                                  + ks * 32 + hi;
                LDSM4(a[i][0], a[i][1], a[i][2], a[i][3], ad);
            }
            #pragma unroll
            for (int g = 0; g < 4; g++) {
                const uint32_t bd = bbase + (g * 64 + wn16 + r16) * 144
                                  + ks * 32 + hi;
                LDSM4(b[g][0], b[g][1], b[g][2], b[g][3], bd);
            }
            #pragma unroll
            for (int i = 0; i < 2; i++)
                #pragma unroll
                for (int g = 0; g < 4; g++) {
                    mma_f16(acc[i][g * 2 + 0], a[i], b[g][0], b[g][2]);
                    mma_f16(acc[i][g * 2 + 1], a[i], b[g][1], b[g][3]);
                }
        }
        if (++st == 3) st = 0;
        if (++stn == 3) stn = 0;
    }

    // ---- fused LSTM epilogue: all 4 gates in-register per thread ----
    #pragma unroll
    for (int i = 0; i < 2; i++) {
        #pragma unroll
        for (int rp = 0; rp < 2; rp++) {
            const int pix = bm * 128 + wm + i * 16 + lr + rp * 8;
            const int r0 = rp * 2;
            float xv[9];
            if (LAYER == 0) {
                const int bb = pix >> 12, y = (pix >> 6) & 63, x = pix & 63;
                #pragma unroll
                for (int tap = 0; tap < 9; tap++) {
                    const int dy = tap / 3 - 1, dx = tap % 3 - 1;
                    const int yy = y + dy, xx = x + dx;
                    xv[tap] = (((unsigned)yy < 64u) && ((unsigned)xx < 64u))
                        ? __ldg(&xin[(long long)(bb * 10 + t) * HWPIX
                                     + yy * 64 + xx])
                        : 0.f;
                }
            }
            #pragma unroll
            for (int jj = 0; jj < 2; jj++) {
                const int f = wn16 + jj * 8 + 2 * lc;
                #pragma unroll
                for (int u = 0; u < 2; u++) {
                    float zi = acc[i][jj][r0 + u]     + __ldg(&bias[f + u]);
                    float zf = acc[i][2 + jj][r0 + u] + __ldg(&bias[64 + f + u]);
                    float zg = acc[i][4 + jj][r0 + u] + __ldg(&bias[128 + f + u]);
                    float zo = acc[i][6 + jj][r0 + u] + __ldg(&bias[192 + f + u]);
                    if (LAYER == 0) {
                        #pragma unroll
                        for (int tap = 0; tap < 9; tap++) {
                            const float kx = xv[tap];
                            zi = fmaf(kx, __ldg(&k0g[tap * 256 + f + u]), zi);
                            zf = fmaf(kx, __ldg(&k0g[tap * 256 + 64 + f + u]), zf);
                            zg = fmaf(kx, __ldg(&k0g[tap * 256 + 128 + f + u]), zg);
                            zo = fmaf(kx, __ldg(&k0g[tap * 256 + 192 + f + u]), zo);
                        }
                    }
                    const long long base = (long long)pix * 64 + f + u;
                    const float cp = cbuf[base];
                    const float cn = hsig(zf) * cp + hsig(zi) * tanhf(zg);
                    const float hn = hsig(zo) * tanhf(cn);
                    cbuf[base] = cn;
                    const __half hr = __float2half(hn);
                    hnext[base] = hr;
                    if (LAYER == 0) {
                        g_seq0[((long long)((pix >> 12) * 10 + t) * HWPIX
                                + (pix & 4095)) * 64 + f + u] = hr;
                    }
                }
            }
        }
    }
}

// ---------------------------------------------------------------------------
extern "C" void kernel_launch(void* const* d_in, const int* in_sizes, int n_in,
                              void* d_out, int out_size)
{
    const float* x   = (const float*)d_in[0];
    const float* k0  = (const float*)d_in[1];
    const float* rk0 = (const float*)d_in[2];
    const float* b0  = (const float*)d_in[3];
    const float* k1  = (const float*)d_in[4];
    const float* rk1 = (const float*)d_in[5];
    const float* b1  = (const float*)d_in[6];
    float* out = (float*)d_out;

    cudaFuncSetAttribute(convlstm_step<0>,
                         cudaFuncAttributeMaxDynamicSharedMemorySize, 165952);
    cudaFuncSetAttribute(convlstm_step<1>,
                         cudaFuncAttributeMaxDynamicSharedMemorySize, 165952);

    zero_state_kernel<<<HC_ELEMS / 256, 256>>>();
    prep_weights<<<(27 * IMGH) / 256, 256>>>(rk0, k1, rk1);

    for (int t = 0; t < 10; ++t) {
        const int pp = t & 1;
        convlstm_step<0><<<256, 512, 165952>>>(t, pp, b0, x, k0);
        convlstm_step<1><<<256, 512, 165952>>>(t, pp, b1, nullptr, nullptr);
    }

    // t=9 wrote with pp=1 -> "a" buffers hold final h
    copy_out_kernel<<<(4 * HC_ELEMS) / 256, 256>>>(out, 1);
}

// round 17
// speedup vs baseline: 6.3920x; 1.1123x over previous
#include <cuda_runtime.h>
#include <cuda_fp16.h>
#include <cstdint>

// ---------------------------------------------------------------------------
// 2-layer ConvLSTM2D, fp16 mma.sync m16n8k16 (fp32 accum) + ldmatrix.x4.
// CTA = 64 pixels x 256 gates, 256 threads / 8 warps (2m x 4n, warp 32x64),
// grid 512, 2 CTAs/SM (independent barrier domains -> latency overlap).
// One chunk = one 3x3 tap (K=64).  B via cp.async.bulk + mbarrier; A via
// cp.async.  2-stage smem ring (R10-proven schedule).  LSTM pointwise fused
// in registers (fp32).  h / seq0 / weights stored fp16.  State buffers
// selected in device code.
// ---------------------------------------------------------------------------

#define HWPIX 4096
#define NPIX 32768
#define HC_ELEMS (NPIX * 64)
#define SEQ_ELEMS (10 * HC_ELEMS)
#define IMGH 18432                   // halfs per B image: 256 n-rows x 72 k(pad)
#define BIMG_BYTES 36864

__device__ __half g_h0a[HC_ELEMS];
__device__ __half g_h0b[HC_ELEMS];
__device__ __half g_h1a[HC_ELEMS];
__device__ __half g_h1b[HC_ELEMS];
__device__ float  g_c0[HC_ELEMS];
__device__ float  g_c1[HC_ELEMS];
__device__ __half g_seq0[SEQ_ELEMS]; // (b,t,y,x,f) fp16
__device__ __half g_Bh0[9 * IMGH];   // layer0 B images [n 256][72]
__device__ __half g_Bh1[18 * IMGH];  // layer1 B images [n 256][72]

// ------------------------------ helpers ------------------------------------
__device__ __forceinline__ uint32_t smem_u32(const void* p) {
    uint32_t a;
    asm("{ .reg .u64 t; cvta.to.shared.u64 t, %1; cvt.u32.u64 %0, t; }"
        : "=r"(a) : "l"(p));
    return a;
}
__device__ __forceinline__ float hsig(float v) {
    return fminf(fmaxf(0.2f * v + 0.5f, 0.f), 1.f);
}
__device__ __forceinline__ void mma_f16(float c[4], const uint32_t a[4],
                                        uint32_t b0, uint32_t b1) {
    asm volatile(
        "mma.sync.aligned.m16n8k16.row.col.f32.f16.f16.f32 "
        "{%0,%1,%2,%3}, {%4,%5,%6,%7}, {%8,%9}, {%0,%1,%2,%3};"
        : "+f"(c[0]), "+f"(c[1]), "+f"(c[2]), "+f"(c[3])
        : "r"(a[0]), "r"(a[1]), "r"(a[2]), "r"(a[3]), "r"(b0), "r"(b1));
}
#define LDSM4(r0, r1, r2, r3, addr) \
    asm volatile("ldmatrix.sync.aligned.m8n8.x4.shared.b16 {%0,%1,%2,%3}, [%4];" \
        : "=r"(r0), "=r"(r1), "=r"(r2), "=r"(r3) : "r"(addr))
#define CP_COMMIT() asm volatile("cp.async.commit_group;" ::: "memory")
#define CP_WAIT0()  asm volatile("cp.async.wait_group 0;" ::: "memory")
#define CP_WAIT1g() asm volatile("cp.async.wait_group 1;" ::: "memory")
#define MB_INIT(mb, n) asm volatile("mbarrier.init.shared.b64 [%0], %1;" \
    :: "r"(mb), "r"(n) : "memory")

__device__ __forceinline__ void mb_wait(uint32_t mb, uint32_t parity) {
    uint32_t done;
    asm volatile("{\n\t.reg .pred p;\n\t"
        "mbarrier.try_wait.parity.acquire.cta.shared::cta.b64 p, [%1], %2;\n\t"
        "selp.b32 %0, 1, 0, p;\n\t}" : "=r"(done) : "r"(mb), "r"(parity) : "memory");
    if (!done) {
        asm volatile("{\n\t.reg .pred P1;\n\t"
            "WL_%=:\n\t"
            "mbarrier.try_wait.parity.acquire.cta.shared::cta.b64 P1, [%0], %1, 0x989680;\n\t"
            "@P1 bra.uni WD_%=;\n\t"
            "bra.uni WL_%=;\n\t"
            "WD_%=:\n\t}" :: "r"(mb), "r"(parity) : "memory");
    }
}

// ------------------------------ small kernels ------------------------------
__global__ void zero_state_kernel() {
    int i = blockIdx.x * 256 + threadIdx.x;
    g_h0a[i] = __float2half(0.f); g_h1a[i] = __float2half(0.f);
    g_c0[i] = 0.f; g_c1[i] = 0.f;
}

// B images: transposed [n 256][k 72 (pad, 64 valid)] per tap, fp16.
__global__ void prep_weights(const float* __restrict__ rk0,
                             const float* __restrict__ k1,
                             const float* __restrict__ rk1) {
    const int i = blockIdx.x * 256 + threadIdx.x;   // < 27*IMGH
    const int img = i / IMGH;
    const int e = i % IMGH;
    const int n = e / 72, k = e % 72;
    float v = 0.f; __half* dst;
    if (img < 9) {
        if (k < 64) v = rk0[(img * 64 + k) * 256 + n];
        dst = g_Bh0 + img * IMGH;
    } else {
        const int c = img - 9;
        if (k < 64)
            v = (c < 9) ? k1[(c * 64 + k) * 256 + n]
                        : rk1[((c - 9) * 64 + k) * 256 + n];
        dst = g_Bh1 + c * IMGH;
    }
    dst[n * 72 + k] = __float2half(v);
}

__global__ void copy_out_kernel(float* __restrict__ out, int pp) {
    const int i = blockIdx.x * 256 + threadIdx.x;
    const int r = i >> 21;
    const int local = i & (HC_ELEMS - 1);
    float v;
    if      (r == 0) v = __half2float(pp ? g_h0a[local] : g_h0b[local]);
    else if (r == 1) v = g_c0[local];
    else if (r == 2) v = __half2float(pp ? g_h1a[local] : g_h1b[local]);
    else             v = g_c1[local];
    out[i] = v;
}

// ------------------------------ main kernel --------------------------------
// smem ring (2 stages): A 64x72 half (9216B) at s*9216,
//                       B 256x72 half (36864B) at 18432 + s*36864,
//                       2 mbarriers at 92160.  Total 92176B.
template<int LAYER>
__global__ __launch_bounds__(256, 2)
void convlstm_step(int t, int pp,
                   const float* __restrict__ bias,
                   const float* __restrict__ xin,
                   const float* __restrict__ k0g)
{
    const __half* hprev; __half* hnext; float* cbuf;
    if (LAYER == 0) {
        hprev = pp ? g_h0b : g_h0a;
        hnext = pp ? g_h0a : g_h0b;
        cbuf  = g_c0;
    } else {
        hprev = pp ? g_h1b : g_h1a;
        hnext = pp ? g_h1a : g_h1b;
        cbuf  = g_c1;
    }

    extern __shared__ float smem[];
    const uint32_t sbase = smem_u32(smem);
    const uint32_t mbb = sbase + 92160u;

    const int tid = threadIdx.x;
    const int lane = tid & 31, wid = tid >> 5;        // wid 0..7
    const int lr = lane >> 2, lc = lane & 3;
    const int wm = (wid >> 2) * 32;          // warp m-base: 0 or 32
    const int wn16 = (wid & 3) * 16;         // warp n-base within each gate
    const int bm = blockIdx.x;               // 0..511

    // A-loader mapping: 4 threads per pixel row, 16 halfs (32B) each
    const int rowA = tid >> 2;               // 0..63
    const int partA = (tid & 3) * 16;        // half offset: 0,16,32,48
    const int m = bm * 64 + rowA;
    const int ab = m >> 12, ay = (m >> 6) & 63, ax = m & 63;

    // ---- hoisted tap geometry ----
    int off9[9];
    int inbm = 0;
    #pragma unroll
    for (int tap = 0; tap < 9; tap++) {
        const int dy = tap / 3 - 1, dx = tap % 3 - 1;
        const int yy = ay + dy, xx = ax + dx;
        if (((unsigned)yy < 64u) && ((unsigned)xx < 64u)) inbm |= (1 << tap);
        const int yc = min(max(yy, 0), 63), xc = min(max(xx, 0), 63);
        off9[tap] = ((yc << 6) + xc) * 64;
    }
    const __half* hbase = hprev + (long long)ab * (HWPIX * 64) + partA;
    const __half* seqb = (LAYER == 1)
        ? g_seq0 + (long long)(ab * 10 + t) * (HWPIX * 64) + partA
        : nullptr;

    const __half* BW = (LAYER == 0) ? g_Bh0 : g_Bh1;
    const int NCH = (LAYER == 0) ? 9 : 18;

    // ---- mbarrier init (one per ring stage) ----
    if (tid == 0) {
        MB_INIT(mbb + 0, 1);
        MB_INIT(mbb + 8, 1);
    }
    __syncthreads();

    float acc[2][8][4];
    #pragma unroll
    for (int i = 0; i < 2; i++)
        #pragma unroll
        for (int j = 0; j < 8; j++)
            #pragma unroll
            for (int r = 0; r < 4; r++) acc[i][j][r] = 0.f;

    // ---- loaders ----
    auto issueB = [&](int ci, int st) {            // tid 0 only: TMA bulk copy
        if (tid == 0) {
            const uint32_t mb = mbb + st * 8;
            const char* src = (const char*)(BW + ci * IMGH);
            const uint32_t dst = sbase + 18432u + st * 36864u;
            asm volatile("mbarrier.arrive.expect_tx.shared.b64 _, [%0], %1;"
                :: "r"(mb), "r"((uint32_t)BIMG_BYTES) : "memory");
            asm volatile(
                "cp.async.bulk.shared::cta.global.mbarrier::complete_tx::bytes "
                "[%0], [%1], %2, [%3];"
                :: "r"(dst), "l"(src), "r"((uint32_t)BIMG_BYTES), "r"(mb)
                : "memory");
        }
    };
    auto issueA = [&](int ci, int st) {
        const __half* base;
        int tap;
        if (LAYER == 1) {
            if (ci < 9) { base = seqb; tap = ci; }
            else        { base = hbase; tap = ci - 9; }
        } else {
            base = hbase; tap = ci;
        }
        const int pr = ((inbm >> tap) & 1) ? 16 : 0;
        const char* ap = (const char*)(base + off9[tap]);
        const uint32_t dst = sbase + st * 9216u + rowA * 144 + (tid & 3) * 32;
        #pragma unroll
        for (int q = 0; q < 2; q++)
            asm volatile("cp.async.ca.shared.global [%0], [%1], 16, %2;"
                :: "r"(dst + q * 16), "l"(ap + q * 16), "r"(pr) : "memory");
    };

    // prologue: chunk 0 into stage 0
    issueB(0, 0); issueA(0, 0); CP_COMMIT();

    // ---- main loop (R10-proven 2-stage schedule: prefetch-1, two syncs) ----
    const int r16 = lane & 15;
    const int hi = (lane >> 4) * 16;
    #pragma unroll 1
    for (int ci = 0; ci < NCH; ci++) {
        const int st = ci & 1;
        if (ci + 1 < NCH) { issueB(ci + 1, st ^ 1); issueA(ci + 1, st ^ 1); }
        CP_COMMIT();
        if (ci == NCH - 1) { CP_WAIT0(); } else { CP_WAIT1g(); }
        mb_wait(mbb + st * 8, (unsigned)(ci >> 1) & 1);
        __syncthreads();

        const uint32_t abase = sbase + st * 9216u;
        const uint32_t bbase = sbase + 18432u + st * 36864u;
        #pragma unroll
        for (int ks = 0; ks < 4; ks++) {            // 4 x k16 = K 64
            uint32_t a[2][4], b[4][4];
            #pragma unroll
            for (int i = 0; i < 2; i++) {
                const uint32_t ad = abase + (wm + i * 16 + r16) * 144
                                  + ks * 32 + hi;
                LDSM4(a[i][0], a[i][1], a[i][2], a[i][3], ad);
            }
            #pragma unroll
            for (int g = 0; g < 4; g++) {
                const uint32_t bd = bbase + (g * 64 + wn16 + r16) * 144
                                  + ks * 32 + hi;
                LDSM4(b[g][0], b[g][1], b[g][2], b[g][3], bd);
            }
            #pragma unroll
            for (int i = 0; i < 2; i++)
                #pragma unroll
                for (int g = 0; g < 4; g++) {
                    mma_f16(acc[i][g * 2 + 0], a[i], b[g][0], b[g][2]);
                    mma_f16(acc[i][g * 2 + 1], a[i], b[g][1], b[g][3]);
                }
        }
        __syncthreads();
    }

    // ---- fused LSTM epilogue: all 4 gates in-register per thread ----
    #pragma unroll
    for (int i = 0; i < 2; i++) {
        #pragma unroll
        for (int rp = 0; rp < 2; rp++) {
            const int pix = bm * 64 + wm + i * 16 + lr + rp * 8;
            const int r0 = rp * 2;
            float xv[9];
            if (LAYER == 0) {
                const int bb = pix >> 12, y = (pix >> 6) & 63, x = pix & 63;
                #pragma unroll
                for (int tap = 0; tap < 9; tap++) {
                    const int dy = tap / 3 - 1, dx = tap % 3 - 1;
                    const int yy = y + dy, xx = x + dx;
                    xv[tap] = (((unsigned)yy < 64u) && ((unsigned)xx < 64u))
                        ? __ldg(&xin[(long long)(bb * 10 + t) * HWPIX
                                     + yy * 64 + xx])
                        : 0.f;
                }
            }
            #pragma unroll
            for (int jj = 0; jj < 2; jj++) {
                const int f = wn16 + jj * 8 + 2 * lc;
                #pragma unroll
                for (int u = 0; u < 2; u++) {
                    float zi = acc[i][jj][r0 + u]     + __ldg(&bias[f + u]);
                    float zf = acc[i][2 + jj][r0 + u] + __ldg(&bias[64 + f + u]);
                    float zg = acc[i][4 + jj][r0 + u] + __ldg(&bias[128 + f + u]);
                    float zo = acc[i][6 + jj][r0 + u] + __ldg(&bias[192 + f + u]);
                    if (LAYER == 0) {
                        #pragma unroll
                        for (int tap = 0; tap < 9; tap++) {
                            const float kx = xv[tap];
                            zi = fmaf(kx, __ldg(&k0g[tap * 256 + f + u]), zi);
                            zf = fmaf(kx, __ldg(&k0g[tap * 256 + 64 + f + u]), zf);
                            zg = fmaf(kx, __ldg(&k0g[tap * 256 + 128 + f + u]), zg);
                            zo = fmaf(kx, __ldg(&k0g[tap * 256 + 192 + f + u]), zo);
                        }
                    }
                    const long long base = (long long)pix * 64 + f + u;
                    const float cp = cbuf[base];
                    const float cn = hsig(zf) * cp + hsig(zi) * tanhf(zg);
                    const float hn = hsig(zo) * tanhf(cn);
                    cbuf[base] = cn;
                    const __half hr = __float2half(hn);
                    hnext[base] = hr;
                    if (LAYER == 0) {
                        g_seq0[((long long)((pix >> 12) * 10 + t) * HWPIX
                                + (pix & 4095)) * 64 + f + u] = hr;
                    }
                }
            }
        }
    }
}

// ---------------------------------------------------------------------------
extern "C" void kernel_launch(void* const* d_in, const int* in_sizes, int n_in,
                              void* d_out, int out_size)
{
    const float* x   = (const float*)d_in[0];
    const float* k0  = (const float*)d_in[1];
    const float* rk0 = (const float*)d_in[2];
    const float* b0  = (const float*)d_in[3];
    const float* k1  = (const float*)d_in[4];
    const float* rk1 = (const float*)d_in[5];
    const float* b1  = (const float*)d_in[6];
    float* out = (float*)d_out;

    cudaFuncSetAttribute(convlstm_step<0>,
                         cudaFuncAttributeMaxDynamicSharedMemorySize, 92176);
    cudaFuncSetAttribute(convlstm_step<1>,
                         cudaFuncAttributeMaxDynamicSharedMemorySize, 92176);

    zero_state_kernel<<<HC_ELEMS / 256, 256>>>();
    prep_weights<<<(27 * IMGH) / 256, 256>>>(rk0, k1, rk1);

    for (int t = 0; t < 10; ++t) {
        const int pp = t & 1;
        convlstm_step<0><<<512, 256, 92176>>>(t, pp, b0, x, k0);
        convlstm_step<1><<<512, 256, 92176>>>(t, pp, b1, nullptr, nullptr);
    }

    // t=9 wrote with pp=1 -> "a" buffers hold final h
    copy_out_kernel<<<(4 * HC_ELEMS) / 256, 256>>>(out, 1);
}